// round 5
// baseline (speedup 1.0000x reference)
#include <cuda_runtime.h>
#include <cuda_bf16.h>
#include <math_constants.h>
#include <cstdint>

// Problem constants
#define B_   2
#define S_   2048
#define D_   1024
#define H_   16
#define HD_  64
#define SCALE_ 0.125f   // 1/sqrt(64)
#define KP_  (3 * D_)   // compensated K' = 3072 for projections
#define AKP_ 192        // compensated K' for QK^T (3*64)

// ============================================================================
// Static device scratch
// ============================================================================
__device__ float g_qkv [(size_t)(B_*S_) * (3*D_)];
__device__ __nv_bfloat16 g_Abig [(size_t)(B_*S_) * KP_];
__device__ __nv_bfloat16 g_W1big[(size_t)(3*D_) * KP_];
__device__ __nv_bfloat16 g_W2big[(size_t)D_ * KP_];
__device__ __nv_bfloat16 g_Qp [(size_t)B_*H_*S_*AKP_];   // [Qh|Ql|Qh], scale folded
__device__ __nv_bfloat16 g_Kp [(size_t)B_*H_*S_*AKP_];   // [Kh|Kh|Kl]
__device__ __nv_bfloat16 g_Vph[(size_t)B_*H_*S_*HD_];
__device__ __nv_bfloat16 g_Vpl[(size_t)B_*H_*S_*HD_];

// ============================================================================
// PTX helpers (sm_80-era only — safe for compute_103 baseline PTX)
// ============================================================================
__device__ __forceinline__ uint32_t smem_u32(const void* p) {
    uint32_t a;
    asm("{ .reg .u64 t; cvta.to.shared.u64 t, %1; cvt.u32.u64 %0, t; }" : "=r"(a) : "l"(p));
    return a;
}
#define CP_ASYNC16(saddr, gptr) \
    asm volatile("cp.async.cg.shared.global [%0], [%1], 16;" :: "r"(saddr), "l"(gptr))
#define CP_COMMIT() asm volatile("cp.async.commit_group;" ::: "memory")
#define CP_WAIT2()  asm volatile("cp.async.wait_group 2;" ::: "memory")
#define CP_WAIT1()  asm volatile("cp.async.wait_group 1;" ::: "memory")
#define CP_WAIT0()  asm volatile("cp.async.wait_group 0;" ::: "memory")
#define LDMATRIX_X4(r0, r1, r2, r3, addr) \
    asm volatile("ldmatrix.sync.aligned.m8n8.x4.shared.b16 {%0,%1,%2,%3}, [%4];" \
        : "=r"(r0), "=r"(r1), "=r"(r2), "=r"(r3) : "r"(addr))
#define LDMATRIX_X4_T(r0, r1, r2, r3, addr) \
    asm volatile("ldmatrix.sync.aligned.m8n8.x4.trans.shared.b16 {%0,%1,%2,%3}, [%4];" \
        : "=r"(r0), "=r"(r1), "=r"(r2), "=r"(r3) : "r"(addr))
#define MMA_BF16(c0, c1, c2, c3, a0, a1, a2, a3, b0, b1) \
    asm volatile("mma.sync.aligned.m16n8k16.row.col.f32.bf16.bf16.f32 " \
        "{%0,%1,%2,%3}, {%4,%5,%6,%7}, {%8,%9}, {%0,%1,%2,%3};" \
        : "+f"(c0), "+f"(c1), "+f"(c2), "+f"(c3) \
        : "r"(a0), "r"(a1), "r"(a2), "r"(a3), "r"(b0), "r"(b1))

__device__ __forceinline__ void pack_pair(float p0, float p1, uint32_t &h, uint32_t &l) {
    __nv_bfloat16 h0 = __float2bfloat16(p0), h1 = __float2bfloat16(p1);
    float r0 = p0 - __bfloat162float(h0);
    float r1 = p1 - __bfloat162float(h1);
    __nv_bfloat16 l0 = __float2bfloat16(r0), l1 = __float2bfloat16(r1);
    h = ((uint32_t)__bfloat16_as_ushort(h1) << 16) | (uint32_t)__bfloat16_as_ushort(h0);
    l = ((uint32_t)__bfloat16_as_ushort(l1) << 16) | (uint32_t)__bfloat16_as_ushort(l0);
}

// ============================================================================
// Prep: bf16 hi/lo 3-term encode for projections
// ============================================================================
__global__ __launch_bounds__(256) void split_a_kernel(
    const float* __restrict__ x, __nv_bfloat16* __restrict__ out, int total)
{
    int i = blockIdx.x * blockDim.x + threadIdx.x;
    if (i >= total) return;
    int r = i >> 10, c = i & (D_ - 1);
    float v = x[i];
    __nv_bfloat16 h = __float2bfloat16(v);
    __nv_bfloat16 l = __float2bfloat16(v - __bfloat162float(h));
    size_t base = (size_t)r * KP_;
    out[base + c]        = h;
    out[base + D_ + c]   = l;
    out[base + 2*D_ + c] = h;
}

__global__ __launch_bounds__(256) void transpose_split_w_kernel(
    const float* __restrict__ w, __nv_bfloat16* __restrict__ out, int N)
{
    __shared__ float tile[32][33];
    int k0 = blockIdx.y * 32, n0 = blockIdx.x * 32;
    int tx = threadIdx.x, ty = threadIdx.y;
    #pragma unroll
    for (int i = 0; i < 32; i += 8)
        tile[ty + i][tx] = w[(size_t)(k0 + ty + i) * N + n0 + tx];
    __syncthreads();
    #pragma unroll
    for (int i = 0; i < 32; i += 8) {
        float x = tile[tx][ty + i];
        __nv_bfloat16 h = __float2bfloat16(x);
        __nv_bfloat16 l = __float2bfloat16(x - __bfloat162float(h));
        size_t o = (size_t)(n0 + ty + i) * KP_ + k0 + tx;
        out[o]        = h;
        out[o + D_]   = h;
        out[o + 2*D_] = l;
    }
}

// ============================================================================
// bf16 mma.sync GEMM: C[M,N] = A'[M,KP] @ W'[N,KP]^T, fp32 accumulate.
// CTA tile 128x128, BK=32, 8 warps of 64x32.
// 4-stage cp.async pipeline (dynamic smem), ONE __syncthreads per K-step.
// ============================================================================
#define GBM 128
#define GBN 128
#define GBK 32
#define SSTRIDE 40   // bf16 elems per smem row (32 + 8 pad, conflict-free LDSM)
#define NSTAGE 4
#define GEMM_SMEM_ELEMS (NSTAGE * (GBM + GBN) * SSTRIDE)
#define GEMM_SMEM_BYTES (GEMM_SMEM_ELEMS * 2)   // 81920

__global__ __launch_bounds__(256) void gemm_mma_kernel(
    const __nv_bfloat16* __restrict__ A,
    const __nv_bfloat16* __restrict__ W,
    float* __restrict__ C, int M, int N)
{
    extern __shared__ __align__(16) __nv_bfloat16 smg[];
    const uint32_t smb = smem_u32(smg);
    // A stage s at elems s*GBM*SSTRIDE; B stage s after all A stages
    const uint32_t aoff = 0;
    const uint32_t boff = NSTAGE * GBM * SSTRIDE;

    const int tid  = threadIdx.x;
    const int wid  = tid >> 5, lane = tid & 31;
    const int m0   = blockIdx.y * GBM;
    const int n0   = blockIdx.x * GBN;
    const int wm   = wid >> 2;
    const int wn   = wid & 3;

    float acc[4][4][4];
    #pragma unroll
    for (int mi = 0; mi < 4; mi++)
        #pragma unroll
        for (int ni = 0; ni < 4; ni++)
            #pragma unroll
            for (int r = 0; r < 4; r++) acc[mi][ni][r] = 0.f;

    const int lr0 = tid >> 2,          lc0 = (tid & 3);
    const int lr1 = (tid + 256) >> 2,  lc1 = (tid & 3);

    auto load_stage = [&](int slot, int kb) {
        const int kt = kb * GBK;
        const uint32_t as = smb + (aoff + (uint32_t)slot * GBM * SSTRIDE) * 2;
        const uint32_t bs = smb + (boff + (uint32_t)slot * GBN * SSTRIDE) * 2;
        CP_ASYNC16(as + (uint32_t)(lr0 * SSTRIDE + lc0 * 8) * 2,
                   A + (size_t)(m0 + lr0) * KP_ + kt + lc0 * 8);
        CP_ASYNC16(as + (uint32_t)(lr1 * SSTRIDE + lc1 * 8) * 2,
                   A + (size_t)(m0 + lr1) * KP_ + kt + lc1 * 8);
        CP_ASYNC16(bs + (uint32_t)(lr0 * SSTRIDE + lc0 * 8) * 2,
                   W + (size_t)(n0 + lr0) * KP_ + kt + lc0 * 8);
        CP_ASYNC16(bs + (uint32_t)(lr1 * SSTRIDE + lc1 * 8) * 2,
                   W + (size_t)(n0 + lr1) * KP_ + kt + lc1 * 8);
    };

    const int NKB = KP_ / GBK;   // 96
    load_stage(0, 0); CP_COMMIT();
    load_stage(1, 1); CP_COMMIT();
    load_stage(2, 2); CP_COMMIT();

    for (int kb = 0; kb < NKB; kb++) {
        const int slot = kb & (NSTAGE - 1);
        CP_WAIT2();          // group kb complete (always-commit numbering)
        __syncthreads();     // all warps done with slot (kb+3)%4 from iter kb-1

        if (kb + 3 < NKB) load_stage((kb + 3) & (NSTAGE - 1), kb + 3);
        CP_COMMIT();         // commit every iter (possibly empty) to keep numbering

        const uint32_t as = smb + (aoff + (uint32_t)slot * GBM * SSTRIDE) * 2;
        const uint32_t bs = smb + (boff + (uint32_t)slot * GBN * SSTRIDE) * 2;

        #pragma unroll
        for (int ks = 0; ks < 2; ks++) {
            uint32_t a[4][4];
            #pragma unroll
            for (int mi = 0; mi < 4; mi++) {
                int row = wm * 64 + mi * 16 + (lane & 15);
                int col = ks * 16 + (lane >> 4) * 8;
                LDMATRIX_X4(a[mi][0], a[mi][1], a[mi][2], a[mi][3],
                            as + (uint32_t)(row * SSTRIDE + col) * 2);
            }
            uint32_t b[4][2];
            #pragma unroll
            for (int nb = 0; nb < 2; nb++) {
                int nrow = wn * 32 + nb * 16 + ((lane & 16) ? 8 : 0) + (lane & 7);
                int kcol = ks * 16 + ((lane & 8) ? 8 : 0);
                uint32_t r0, r1, r2, r3;
                LDMATRIX_X4(r0, r1, r2, r3,
                            bs + (uint32_t)(nrow * SSTRIDE + kcol) * 2);
                b[nb*2][0] = r0; b[nb*2][1] = r1;
                b[nb*2+1][0] = r2; b[nb*2+1][1] = r3;
            }
            #pragma unroll
            for (int mi = 0; mi < 4; mi++)
                #pragma unroll
                for (int ni = 0; ni < 4; ni++)
                    MMA_BF16(acc[mi][ni][0], acc[mi][ni][1], acc[mi][ni][2], acc[mi][ni][3],
                             a[mi][0], a[mi][1], a[mi][2], a[mi][3],
                             b[ni][0], b[ni][1]);
        }
    }

    #pragma unroll
    for (int mi = 0; mi < 4; mi++) {
        int mrow = m0 + wm * 64 + mi * 16 + (lane >> 2);
        #pragma unroll
        for (int ni = 0; ni < 4; ni++) {
            int ncol = n0 + wn * 32 + ni * 8 + (lane & 3) * 2;
            *(float2*)&C[(size_t)mrow * N + ncol] =
                make_float2(acc[mi][ni][0], acc[mi][ni][1]);
            *(float2*)&C[(size_t)(mrow + 8) * N + ncol] =
                make_float2(acc[mi][ni][2], acc[mi][ni][3]);
        }
    }
}

// ============================================================================
// RoPE -> tensor-ready bf16 operands (unchanged from R4)
// ============================================================================
__global__ __launch_bounds__(256) void rope_pack_kernel(
    const float* __restrict__ qkv,
    const float* __restrict__ sin_q, const float* __restrict__ cos_q,
    const float* __restrict__ sin_k, const float* __restrict__ cos_k,
    __nv_bfloat16* __restrict__ Qp, __nv_bfloat16* __restrict__ Kp,
    __nv_bfloat16* __restrict__ Vph, __nv_bfloat16* __restrict__ Vpl)
{
    int idx = blockIdx.x * blockDim.x + threadIdx.x;
    if (idx >= B_*S_*D_) return;
    int d = idx % HD_;
    int h = (idx / HD_) % H_;
    int s = (idx / D_) % S_;
    int b = idx / (S_ * D_);

    const float* row = qkv + ((size_t)b*S_ + s) * (3*D_);
    int hd = h*HD_ + d;
    int dp = (d < HD_/2) ? d + HD_/2 : d - HD_/2;
    float sgn = (d < HD_/2) ? -1.f : 1.f;

    float qv = row[hd];
    float kv = row[D_ + hd];
    float vv = row[2*D_ + hd];
    float qp = row[h*HD_ + dp];
    float kp = row[D_ + h*HD_ + dp];

    float sq = sin_q[s*HD_ + d], cq = cos_q[s*HD_ + d];
    float sk = sin_k[s*HD_ + d], ck = cos_k[s*HD_ + d];

    float qr = (qv * cq + sgn * qp * sq) * SCALE_;
    float kr = kv * ck + sgn * kp * sk;

    size_t bhs = ((size_t)(b*H_ + h) * S_ + s);

    __nv_bfloat16 qh = __float2bfloat16(qr);
    __nv_bfloat16 ql = __float2bfloat16(qr - __bfloat162float(qh));
    __nv_bfloat16 kh = __float2bfloat16(kr);
    __nv_bfloat16 kl = __float2bfloat16(kr - __bfloat162float(kh));
    __nv_bfloat16 vh = __float2bfloat16(vv);
    __nv_bfloat16 vl = __float2bfloat16(vv - __bfloat162float(vh));

    __nv_bfloat16* qrow = Qp + bhs * AKP_;
    qrow[d] = qh; qrow[64 + d] = ql; qrow[128 + d] = qh;
    __nv_bfloat16* krow = Kp + bhs * AKP_;
    krow[d] = kh; krow[64 + d] = kh; krow[128 + d] = kl;
    Vph[bhs * HD_ + d] = vh;
    Vpl[bhs * HD_ + d] = vl;
}

// ============================================================================
// Tensor-core causal flash attention (R4 mainloop).
// NEW: epilogue writes the 3-term bf16 A' encoding directly (fuses split_a).
// ============================================================================
#define AQ 128
#define AK 32
#define QSTR 200
#define VSTR 72

#define QS_OFF   0
#define KS_OFF   25600
#define KS_STAGE 6400
#define VH_OFF   38400
#define VS_STAGE 2304
#define VL_OFF   43008
#define ATTN_SMEM_BYTES ((VL_OFF + 2*VS_STAGE) * 2)   // 95232

__global__ __launch_bounds__(128) void attn_mma_kernel(
    const __nv_bfloat16* __restrict__ Qp, const __nv_bfloat16* __restrict__ Kp,
    const __nv_bfloat16* __restrict__ Vph, const __nv_bfloat16* __restrict__ Vpl,
    __nv_bfloat16* __restrict__ Aout)   // [B*S, KP] 3-term encoded
{
    extern __shared__ __align__(16) __nv_bfloat16 sm[];
    const uint32_t smb = smem_u32(sm);

    const int tid  = threadIdx.x;
    const int wid  = tid >> 5, lane = tid & 31;
    const int bh   = blockIdx.y;
    const int q0   = blockIdx.x * AQ;
    const int qrow0 = q0 + 32 * wid;

    const size_t bhS = (size_t)bh * S_;

    auto load_q = [&]() {
        #pragma unroll
        for (int i = 0; i < 24; i++) {
            int idx = tid + i * 128;
            int row = idx / 24, c = idx % 24;
            CP_ASYNC16(smb + (uint32_t)(QS_OFF + row * QSTR + c * 8) * 2,
                       Qp + (bhS + q0 + row) * AKP_ + c * 8);
        }
    };
    auto load_kv = [&](int stage, int kt) {
        int s0 = kt * AK;
        #pragma unroll
        for (int i = 0; i < 6; i++) {
            int idx = tid + i * 128;
            int row = idx / 24, c = idx % 24;
            CP_ASYNC16(smb + (uint32_t)(KS_OFF + stage * KS_STAGE + row * QSTR + c * 8) * 2,
                       Kp + (bhS + s0 + row) * AKP_ + c * 8);
        }
        #pragma unroll
        for (int i = 0; i < 2; i++) {
            int idx = tid + i * 128;
            int row = idx / 8, c = idx % 8;
            CP_ASYNC16(smb + (uint32_t)(VH_OFF + stage * VS_STAGE + row * VSTR + c * 8) * 2,
                       Vph + (bhS + s0 + row) * HD_ + c * 8);
            CP_ASYNC16(smb + (uint32_t)(VL_OFF + stage * VS_STAGE + row * VSTR + c * 8) * 2,
                       Vpl + (bhS + s0 + row) * HD_ + c * 8);
        }
    };

    float O[2][8][4];
    #pragma unroll
    for (int mi = 0; mi < 2; mi++)
        #pragma unroll
        for (int nd = 0; nd < 8; nd++)
            #pragma unroll
            for (int r = 0; r < 4; r++) O[mi][nd][r] = 0.f;
    float mst[2][2] = {{-CUDART_INF_F, -CUDART_INF_F}, {-CUDART_INF_F, -CUDART_INF_F}};
    float lst[2][2] = {{0.f, 0.f}, {0.f, 0.f}};

    const int ntiles = q0 / AK + 4;

    load_q();
    CP_COMMIT();
    load_kv(0, 0);
    CP_COMMIT();

    for (int kt = 0; kt < ntiles; kt++) {
        const int stage = kt & 1;
        if (kt + 1 < ntiles) {
            load_kv((kt + 1) & 1, kt + 1);
            CP_COMMIT();
            CP_WAIT1();
        } else {
            CP_WAIT0();
        }
        __syncthreads();

        const int k0g = kt * AK;
        const bool active = (k0g <= qrow0 + 31);

        if (active) {
            float c[2][4][4];
            #pragma unroll
            for (int mi = 0; mi < 2; mi++)
                #pragma unroll
                for (int ni = 0; ni < 4; ni++)
                    #pragma unroll
                    for (int r = 0; r < 4; r++) c[mi][ni][r] = 0.f;

            #pragma unroll
            for (int kc = 0; kc < 12; kc++) {
                uint32_t kb[4][2];
                #pragma unroll
                for (int t = 0; t < 2; t++) {
                    int krow = 16*t + (lane & 7) + 8*(lane >> 4);
                    int kcol = kc*16 + 8*((lane >> 3) & 1);
                    uint32_t r0, r1, r2, r3;
                    LDMATRIX_X4(r0, r1, r2, r3,
                        smb + (uint32_t)(KS_OFF + stage*KS_STAGE + krow*QSTR + kcol) * 2);
                    kb[2*t][0] = r0; kb[2*t][1] = r1;
                    kb[2*t+1][0] = r2; kb[2*t+1][1] = r3;
                }
                #pragma unroll
                for (int mi = 0; mi < 2; mi++) {
                    int qrow = 32*wid + 16*mi + (lane & 15);
                    int qcol = kc*16 + 8*(lane >> 4);
                    uint32_t a0, a1, a2, a3;
                    LDMATRIX_X4(a0, a1, a2, a3,
                        smb + (uint32_t)(QS_OFF + qrow*QSTR + qcol) * 2);
                    #pragma unroll
                    for (int ni = 0; ni < 4; ni++)
                        MMA_BF16(c[mi][ni][0], c[mi][ni][1], c[mi][ni][2], c[mi][ni][3],
                                 a0, a1, a2, a3, kb[ni][0], kb[ni][1]);
                }
            }

            if (k0g + AK - 1 > qrow0) {
                #pragma unroll
                for (int mi = 0; mi < 2; mi++)
                    #pragma unroll
                    for (int ni = 0; ni < 4; ni++)
                        #pragma unroll
                        for (int r = 0; r < 4; r++) {
                            int kk = k0g + ni*8 + 2*(lane & 3) + (r & 1);
                            int qq = qrow0 + 16*mi + (lane >> 2) + ((r >= 2) ? 8 : 0);
                            if (kk > qq) c[mi][ni][r] = -CUDART_INF_F;
                        }
            }

            #pragma unroll
            for (int mi = 0; mi < 2; mi++)
                #pragma unroll
                for (int h = 0; h < 2; h++) {
                    float mt = -CUDART_INF_F;
                    #pragma unroll
                    for (int ni = 0; ni < 4; ni++)
                        mt = fmaxf(mt, fmaxf(c[mi][ni][2*h], c[mi][ni][2*h+1]));
                    mt = fmaxf(mt, __shfl_xor_sync(0xffffffffu, mt, 1));
                    mt = fmaxf(mt, __shfl_xor_sync(0xffffffffu, mt, 2));
                    float mnew = fmaxf(mst[mi][h], mt);
                    float corr = __expf(mst[mi][h] - mnew);
                    mst[mi][h] = mnew;
                    float ls = 0.f;
                    #pragma unroll
                    for (int ni = 0; ni < 4; ni++) {
                        float p0 = __expf(c[mi][ni][2*h]   - mnew);
                        float p1 = __expf(c[mi][ni][2*h+1] - mnew);
                        c[mi][ni][2*h] = p0; c[mi][ni][2*h+1] = p1;
                        ls += p0 + p1;
                    }
                    lst[mi][h] = lst[mi][h] * corr + ls;
                    #pragma unroll
                    for (int nd = 0; nd < 8; nd++) {
                        O[mi][nd][2*h]   *= corr;
                        O[mi][nd][2*h+1] *= corr;
                    }
                }

            #pragma unroll
            for (int kc2 = 0; kc2 < 2; kc2++) {
                uint32_t ph[2][4], pl[2][4];
                #pragma unroll
                for (int mi = 0; mi < 2; mi++) {
                    pack_pair(c[mi][2*kc2][0],   c[mi][2*kc2][1],   ph[mi][0], pl[mi][0]);
                    pack_pair(c[mi][2*kc2][2],   c[mi][2*kc2][3],   ph[mi][1], pl[mi][1]);
                    pack_pair(c[mi][2*kc2+1][0], c[mi][2*kc2+1][1], ph[mi][2], pl[mi][2]);
                    pack_pair(c[mi][2*kc2+1][2], c[mi][2*kc2+1][3], ph[mi][3], pl[mi][3]);
                }
                uint32_t vh[8][2], vl[8][2];
                #pragma unroll
                for (int t = 0; t < 4; t++) {
                    int vrow = kc2*16 + (lane & 15);
                    int vcol = 16*t + 8*(lane >> 4);
                    uint32_t r0, r1, r2, r3;
                    LDMATRIX_X4_T(r0, r1, r2, r3,
                        smb + (uint32_t)(VH_OFF + stage*VS_STAGE + vrow*VSTR + vcol) * 2);
                    vh[2*t][0] = r0; vh[2*t][1] = r1;
                    vh[2*t+1][0] = r2; vh[2*t+1][1] = r3;
                    LDMATRIX_X4_T(r0, r1, r2, r3,
                        smb + (uint32_t)(VL_OFF + stage*VS_STAGE + vrow*VSTR + vcol) * 2);
                    vl[2*t][0] = r0; vl[2*t][1] = r1;
                    vl[2*t+1][0] = r2; vl[2*t+1][1] = r3;
                }
                #pragma unroll
                for (int mi = 0; mi < 2; mi++)
                    #pragma unroll
                    for (int nd = 0; nd < 8; nd++) {
                        MMA_BF16(O[mi][nd][0], O[mi][nd][1], O[mi][nd][2], O[mi][nd][3],
                                 ph[mi][0], ph[mi][1], ph[mi][2], ph[mi][3],
                                 vh[nd][0], vh[nd][1]);
                        MMA_BF16(O[mi][nd][0], O[mi][nd][1], O[mi][nd][2], O[mi][nd][3],
                                 ph[mi][0], ph[mi][1], ph[mi][2], ph[mi][3],
                                 vl[nd][0], vl[nd][1]);
                        MMA_BF16(O[mi][nd][0], O[mi][nd][1], O[mi][nd][2], O[mi][nd][3],
                                 pl[mi][0], pl[mi][1], pl[mi][2], pl[mi][3],
                                 vh[nd][0], vh[nd][1]);
                    }
            }
        }
        __syncthreads();
    }

    // ---- normalize + write 3-term bf16 A' rows directly (fused split) ----
    const int b = bh >> 4, hh = bh & 15;
    #pragma unroll
    for (int mi = 0; mi < 2; mi++)
        #pragma unroll
        for (int h = 0; h < 2; h++) {
            float lt = lst[mi][h];
            lt += __shfl_xor_sync(0xffffffffu, lt, 1);
            lt += __shfl_xor_sync(0xffffffffu, lt, 2);
            float inv = 1.f / lt;
            int row = qrow0 + 16*mi + (lane >> 2) + ((h) ? 8 : 0);
            size_t rbase = ((size_t)b*S_ + row) * KP_;
            #pragma unroll
            for (int nd = 0; nd < 8; nd++) {
                int col = hh * HD_ + nd*8 + 2*(lane & 3);
                uint32_t phi, plo;
                pack_pair(O[mi][nd][2*h] * inv, O[mi][nd][2*h+1] * inv, phi, plo);
                *(uint32_t*)&Aout[rbase + col]          = phi;
                *(uint32_t*)&Aout[rbase + D_ + col]     = plo;
                *(uint32_t*)&Aout[rbase + 2*D_ + col]   = phi;
            }
        }
}

// ============================================================================
// Launch
// ============================================================================
extern "C" void kernel_launch(void* const* d_in, const int* in_sizes, int n_in,
                              void* d_out, int out_size)
{
    const float* query = (const float*)d_in[0];
    const float* sin_q = (const float*)d_in[1];
    const float* cos_q = (const float*)d_in[2];
    const float* sin_k = (const float*)d_in[3];
    const float* cos_k = (const float*)d_in[4];
    const float* w_in  = (const float*)d_in[5];
    const float* w_out = (const float*)d_in[6];
    float* out = (float*)d_out;

    float *qkv;
    __nv_bfloat16 *Abig, *W1big, *W2big, *Qp, *Kp, *Vph, *Vpl;
    cudaGetSymbolAddress((void**)&qkv,   g_qkv);
    cudaGetSymbolAddress((void**)&Abig,  g_Abig);
    cudaGetSymbolAddress((void**)&W1big, g_W1big);
    cudaGetSymbolAddress((void**)&W2big, g_W2big);
    cudaGetSymbolAddress((void**)&Qp,    g_Qp);
    cudaGetSymbolAddress((void**)&Kp,    g_Kp);
    cudaGetSymbolAddress((void**)&Vph,   g_Vph);
    cudaGetSymbolAddress((void**)&Vpl,   g_Vpl);

    static bool attr_set = false;
    if (!attr_set) {
        cudaFuncSetAttribute(attn_mma_kernel,
                             cudaFuncAttributeMaxDynamicSharedMemorySize, ATTN_SMEM_BYTES);
        cudaFuncSetAttribute(gemm_mma_kernel,
                             cudaFuncAttributeMaxDynamicSharedMemorySize, GEMM_SMEM_BYTES);
        attr_set = true;
    }

    const int M = B_ * S_;   // 4096

    // Prep: 3-term bf16 encode
    split_a_kernel<<<(M*D_ + 255)/256, 256>>>(query, Abig, M*D_);
    transpose_split_w_kernel<<<dim3(3*D_/32, D_/32), dim3(32,8)>>>(w_in,  W1big, 3*D_);
    transpose_split_w_kernel<<<dim3(D_/32,   D_/32), dim3(32,8)>>>(w_out, W2big, D_);

    // 1) QKV projection (tensor cores, 4-stage pipeline)
    gemm_mma_kernel<<<dim3(3*D_/GBN, M/GBM), 256, GEMM_SMEM_BYTES>>>(Abig, W1big, qkv, M, 3*D_);

    // 2) RoPE + pack tensor operands
    rope_pack_kernel<<<(B_*S_*D_ + 255)/256, 256>>>(
        qkv, sin_q, cos_q, sin_k, cos_k, Qp, Kp, Vph, Vpl);

    // 3) Tensor-core causal flash attention (writes A' for out-proj directly)
    attn_mma_kernel<<<dim3(S_/AQ, B_*H_), 128, ATTN_SMEM_BYTES>>>(Qp, Kp, Vph, Vpl, Abig);

    // 4) Output projection (tensor cores, 4-stage pipeline)
    gemm_mma_kernel<<<dim3(D_/GBN, M/GBM), 256, GEMM_SMEM_BYTES>>>(Abig, W2big, out, M, D_);
}

// round 6
// speedup vs baseline: 1.2965x; 1.2965x over previous
#include <cuda_runtime.h>
#include <cuda_bf16.h>
#include <cuda_fp16.h>
#include <math_constants.h>
#include <cstdint>

// Problem constants
#define B_   2
#define S_   2048
#define D_   1024
#define H_   16
#define HD_  64
#define SCALE_ 0.125f   // 1/sqrt(64)
#define KP2_ (2 * D_)   // fp16 2-term K' = 2048 for projections
#define AKP_ 192        // bf16 3-term K' for QK^T (3*64)

// ============================================================================
// Static device scratch
// ============================================================================
__device__ float g_qkv [(size_t)(B_*S_) * (3*D_)];
__device__ __half g_Abig [(size_t)(B_*S_) * KP2_];      // [4096, 2048] fp16
__device__ __half g_W1big[(size_t)(3*D_) * KP2_];       // [3072, 2048] fp16
__device__ __half g_W2big[(size_t)D_ * KP2_];           // [1024, 2048] fp16
__device__ __nv_bfloat16 g_Qp [(size_t)B_*H_*S_*AKP_];  // [Qh|Ql|Qh], scale folded
__device__ __nv_bfloat16 g_Kp [(size_t)B_*H_*S_*AKP_];  // [Kh|Kh|Kl]
__device__ __nv_bfloat16 g_Vph[(size_t)B_*H_*S_*HD_];
__device__ __nv_bfloat16 g_Vpl[(size_t)B_*H_*S_*HD_];

// ============================================================================
// PTX helpers (sm_80-era only — safe for compute_103 baseline PTX)
// ============================================================================
__device__ __forceinline__ uint32_t smem_u32(const void* p) {
    uint32_t a;
    asm("{ .reg .u64 t; cvta.to.shared.u64 t, %1; cvt.u32.u64 %0, t; }" : "=r"(a) : "l"(p));
    return a;
}
#define CP_ASYNC16(saddr, gptr) \
    asm volatile("cp.async.cg.shared.global [%0], [%1], 16;" :: "r"(saddr), "l"(gptr))
#define CP_COMMIT() asm volatile("cp.async.commit_group;" ::: "memory")
#define CP_WAIT1()  asm volatile("cp.async.wait_group 1;" ::: "memory")
#define CP_WAIT0()  asm volatile("cp.async.wait_group 0;" ::: "memory")
#define LDMATRIX_X4(r0, r1, r2, r3, addr) \
    asm volatile("ldmatrix.sync.aligned.m8n8.x4.shared.b16 {%0,%1,%2,%3}, [%4];" \
        : "=r"(r0), "=r"(r1), "=r"(r2), "=r"(r3) : "r"(addr))
#define LDMATRIX_X4_T(r0, r1, r2, r3, addr) \
    asm volatile("ldmatrix.sync.aligned.m8n8.x4.trans.shared.b16 {%0,%1,%2,%3}, [%4];" \
        : "=r"(r0), "=r"(r1), "=r"(r2), "=r"(r3) : "r"(addr))
#define MMA_BF16(c0, c1, c2, c3, a0, a1, a2, a3, b0, b1) \
    asm volatile("mma.sync.aligned.m16n8k16.row.col.f32.bf16.bf16.f32 " \
        "{%0,%1,%2,%3}, {%4,%5,%6,%7}, {%8,%9}, {%0,%1,%2,%3};" \
        : "+f"(c0), "+f"(c1), "+f"(c2), "+f"(c3) \
        : "r"(a0), "r"(a1), "r"(a2), "r"(a3), "r"(b0), "r"(b1))
#define MMA_F16(c0, c1, c2, c3, a0, a1, a2, a3, b0, b1) \
    asm volatile("mma.sync.aligned.m16n8k16.row.col.f32.f16.f16.f32 " \
        "{%0,%1,%2,%3}, {%4,%5,%6,%7}, {%8,%9}, {%0,%1,%2,%3};" \
        : "+f"(c0), "+f"(c1), "+f"(c2), "+f"(c3) \
        : "r"(a0), "r"(a1), "r"(a2), "r"(a3), "r"(b0), "r"(b1))

// bf16 hi/lo pack (attention P fragments)
__device__ __forceinline__ void pack_pair(float p0, float p1, uint32_t &h, uint32_t &l) {
    __nv_bfloat16 h0 = __float2bfloat16(p0), h1 = __float2bfloat16(p1);
    float r0 = p0 - __bfloat162float(h0);
    float r1 = p1 - __bfloat162float(h1);
    __nv_bfloat16 l0 = __float2bfloat16(r0), l1 = __float2bfloat16(r1);
    h = ((uint32_t)__bfloat16_as_ushort(h1) << 16) | (uint32_t)__bfloat16_as_ushort(h0);
    l = ((uint32_t)__bfloat16_as_ushort(l1) << 16) | (uint32_t)__bfloat16_as_ushort(l0);
}
// fp16 hi/lo pack (attention epilogue -> A')
__device__ __forceinline__ void pack_pair_h(float p0, float p1, uint32_t &h, uint32_t &l) {
    __half h0 = __float2half_rn(p0), h1 = __float2half_rn(p1);
    float r0 = p0 - __half2float(h0);
    float r1 = p1 - __half2float(h1);
    __half l0 = __float2half_rn(r0), l1 = __float2half_rn(r1);
    h = ((uint32_t)__half_as_ushort(h1) << 16) | (uint32_t)__half_as_ushort(h0);
    l = ((uint32_t)__half_as_ushort(l1) << 16) | (uint32_t)__half_as_ushort(l0);
}

// ============================================================================
// Prep: fp16 2-term encode for projections
// A' [M, 2D]: [hi | lo]   (exact: hi+lo == x to 2^-24)
// W' [N, 2D]: [hi | hi]   (error = W fp16 rounding ~1.4e-4)
// ============================================================================
__global__ __launch_bounds__(256) void split_a_kernel(
    const float* __restrict__ x, __half* __restrict__ out, int total)
{
    int i = blockIdx.x * blockDim.x + threadIdx.x;
    if (i >= total) return;
    int r = i >> 10, c = i & (D_ - 1);
    float v = x[i];
    __half h = __float2half_rn(v);
    __half l = __float2half_rn(v - __half2float(h));
    size_t base = (size_t)r * KP2_;
    out[base + c]      = h;
    out[base + D_ + c] = l;
}

__global__ __launch_bounds__(256) void transpose_split_w_kernel(
    const float* __restrict__ w, __half* __restrict__ out, int N)
{
    __shared__ float tile[32][33];
    int k0 = blockIdx.y * 32, n0 = blockIdx.x * 32;
    int tx = threadIdx.x, ty = threadIdx.y;
    #pragma unroll
    for (int i = 0; i < 32; i += 8)
        tile[ty + i][tx] = w[(size_t)(k0 + ty + i) * N + n0 + tx];
    __syncthreads();
    #pragma unroll
    for (int i = 0; i < 32; i += 8) {
        float x = tile[tx][ty + i];
        __half h = __float2half_rn(x);
        size_t o = (size_t)(n0 + ty + i) * KP2_ + k0 + tx;
        out[o]      = h;
        out[o + D_] = h;
    }
}

// ============================================================================
// fp16 mma.sync GEMM: C[M,N] = A'[M,KP2] @ W'[N,KP2]^T, fp32 accumulate.
// R4-proven structure: CTA 128x128, BK=32, 8 warps of 64x32, 2-stage cp.async.
// ============================================================================
#define GBM 128
#define GBN 128
#define GBK 32
#define SSTRIDE 40   // halves per smem row (32 + 8 pad, conflict-free LDSM)

__global__ __launch_bounds__(256) void gemm_mma_kernel(
    const __half* __restrict__ A,
    const __half* __restrict__ W,
    float* __restrict__ C, int M, int N)
{
    __shared__ __half As[2][GBM * SSTRIDE];
    __shared__ __half Bs[2][GBN * SSTRIDE];

    const int tid  = threadIdx.x;
    const int wid  = tid >> 5, lane = tid & 31;
    const int m0   = blockIdx.y * GBM;
    const int n0   = blockIdx.x * GBN;
    const int wm   = wid >> 2;
    const int wn   = wid & 3;

    float acc[4][4][4];
    #pragma unroll
    for (int mi = 0; mi < 4; mi++)
        #pragma unroll
        for (int ni = 0; ni < 4; ni++)
            #pragma unroll
            for (int r = 0; r < 4; r++) acc[mi][ni][r] = 0.f;

    const uint32_t as0 = smem_u32(&As[0][0]), as1 = smem_u32(&As[1][0]);
    const uint32_t bs0 = smem_u32(&Bs[0][0]), bs1 = smem_u32(&Bs[1][0]);

    const int lr0 = tid >> 2,          lc0 = (tid & 3);
    const int lr1 = (tid + 256) >> 2,  lc1 = (tid & 3);

    auto load_stage = [&](int stage, int kb) {
        const int kt = kb * GBK;
        const uint32_t as = stage ? as1 : as0;
        const uint32_t bs = stage ? bs1 : bs0;
        CP_ASYNC16(as + (uint32_t)(lr0 * SSTRIDE + lc0 * 8) * 2,
                   A + (size_t)(m0 + lr0) * KP2_ + kt + lc0 * 8);
        CP_ASYNC16(as + (uint32_t)(lr1 * SSTRIDE + lc1 * 8) * 2,
                   A + (size_t)(m0 + lr1) * KP2_ + kt + lc1 * 8);
        CP_ASYNC16(bs + (uint32_t)(lr0 * SSTRIDE + lc0 * 8) * 2,
                   W + (size_t)(n0 + lr0) * KP2_ + kt + lc0 * 8);
        CP_ASYNC16(bs + (uint32_t)(lr1 * SSTRIDE + lc1 * 8) * 2,
                   W + (size_t)(n0 + lr1) * KP2_ + kt + lc1 * 8);
    };

    const int NKB = KP2_ / GBK;   // 64
    load_stage(0, 0);
    CP_COMMIT();

    for (int kb = 0; kb < NKB; kb++) {
        if (kb + 1 < NKB) {
            load_stage((kb + 1) & 1, kb + 1);
            CP_COMMIT();
            CP_WAIT1();
        } else {
            CP_WAIT0();
        }
        __syncthreads();

        const uint32_t as = (kb & 1) ? as1 : as0;
        const uint32_t bs = (kb & 1) ? bs1 : bs0;

        #pragma unroll
        for (int ks = 0; ks < 2; ks++) {
            uint32_t a[4][4];
            #pragma unroll
            for (int mi = 0; mi < 4; mi++) {
                int row = wm * 64 + mi * 16 + (lane & 15);
                int col = ks * 16 + (lane >> 4) * 8;
                LDMATRIX_X4(a[mi][0], a[mi][1], a[mi][2], a[mi][3],
                            as + (uint32_t)(row * SSTRIDE + col) * 2);
            }
            uint32_t b[4][2];
            #pragma unroll
            for (int nb = 0; nb < 2; nb++) {
                int nrow = wn * 32 + nb * 16 + ((lane & 16) ? 8 : 0) + (lane & 7);
                int kcol = ks * 16 + ((lane & 8) ? 8 : 0);
                uint32_t r0, r1, r2, r3;
                LDMATRIX_X4(r0, r1, r2, r3,
                            bs + (uint32_t)(nrow * SSTRIDE + kcol) * 2);
                b[nb*2][0] = r0; b[nb*2][1] = r1;
                b[nb*2+1][0] = r2; b[nb*2+1][1] = r3;
            }
            #pragma unroll
            for (int mi = 0; mi < 4; mi++)
                #pragma unroll
                for (int ni = 0; ni < 4; ni++)
                    MMA_F16(acc[mi][ni][0], acc[mi][ni][1], acc[mi][ni][2], acc[mi][ni][3],
                            a[mi][0], a[mi][1], a[mi][2], a[mi][3],
                            b[ni][0], b[ni][1]);
        }
        __syncthreads();
    }

    #pragma unroll
    for (int mi = 0; mi < 4; mi++) {
        int mrow = m0 + wm * 64 + mi * 16 + (lane >> 2);
        #pragma unroll
        for (int ni = 0; ni < 4; ni++) {
            int ncol = n0 + wn * 32 + ni * 8 + (lane & 3) * 2;
            *(float2*)&C[(size_t)mrow * N + ncol] =
                make_float2(acc[mi][ni][0], acc[mi][ni][1]);
            *(float2*)&C[(size_t)(mrow + 8) * N + ncol] =
                make_float2(acc[mi][ni][2], acc[mi][ni][3]);
        }
    }
}

// ============================================================================
// RoPE -> tensor-ready bf16 operands (unchanged from R4)
// ============================================================================
__global__ __launch_bounds__(256) void rope_pack_kernel(
    const float* __restrict__ qkv,
    const float* __restrict__ sin_q, const float* __restrict__ cos_q,
    const float* __restrict__ sin_k, const float* __restrict__ cos_k,
    __nv_bfloat16* __restrict__ Qp, __nv_bfloat16* __restrict__ Kp,
    __nv_bfloat16* __restrict__ Vph, __nv_bfloat16* __restrict__ Vpl)
{
    int idx = blockIdx.x * blockDim.x + threadIdx.x;
    if (idx >= B_*S_*D_) return;
    int d = idx % HD_;
    int h = (idx / HD_) % H_;
    int s = (idx / D_) % S_;
    int b = idx / (S_ * D_);

    const float* row = qkv + ((size_t)b*S_ + s) * (3*D_);
    int hd = h*HD_ + d;
    int dp = (d < HD_/2) ? d + HD_/2 : d - HD_/2;
    float sgn = (d < HD_/2) ? -1.f : 1.f;

    float qv = row[hd];
    float kv = row[D_ + hd];
    float vv = row[2*D_ + hd];
    float qp = row[h*HD_ + dp];
    float kp = row[D_ + h*HD_ + dp];

    float sq = sin_q[s*HD_ + d], cq = cos_q[s*HD_ + d];
    float sk = sin_k[s*HD_ + d], ck = cos_k[s*HD_ + d];

    float qr = (qv * cq + sgn * qp * sq) * SCALE_;
    float kr = kv * ck + sgn * kp * sk;

    size_t bhs = ((size_t)(b*H_ + h) * S_ + s);

    __nv_bfloat16 qh = __float2bfloat16(qr);
    __nv_bfloat16 ql = __float2bfloat16(qr - __bfloat162float(qh));
    __nv_bfloat16 kh = __float2bfloat16(kr);
    __nv_bfloat16 kl = __float2bfloat16(kr - __bfloat162float(kh));
    __nv_bfloat16 vh = __float2bfloat16(vv);
    __nv_bfloat16 vl = __float2bfloat16(vv - __bfloat162float(vh));

    __nv_bfloat16* qrow = Qp + bhs * AKP_;
    qrow[d] = qh; qrow[64 + d] = ql; qrow[128 + d] = qh;
    __nv_bfloat16* krow = Kp + bhs * AKP_;
    krow[d] = kh; krow[64 + d] = kh; krow[128 + d] = kl;
    Vph[bhs * HD_ + d] = vh;
    Vpl[bhs * HD_ + d] = vl;
}

// ============================================================================
// Tensor-core causal flash attention (R4 mainloop, known-good).
// Epilogue writes fp16 2-term A' rows for the output projection.
// ============================================================================
#define AQ 128
#define AK 32
#define QSTR 200
#define VSTR 72

#define QS_OFF   0
#define KS_OFF   25600
#define KS_STAGE 6400
#define VH_OFF   38400
#define VS_STAGE 2304
#define VL_OFF   43008
#define ATTN_SMEM_BYTES ((VL_OFF + 2*VS_STAGE) * 2)   // 95232

__global__ __launch_bounds__(128) void attn_mma_kernel(
    const __nv_bfloat16* __restrict__ Qp, const __nv_bfloat16* __restrict__ Kp,
    const __nv_bfloat16* __restrict__ Vph, const __nv_bfloat16* __restrict__ Vpl,
    __half* __restrict__ Aout)   // [B*S, KP2] fp16 2-term encoded
{
    extern __shared__ __align__(16) __nv_bfloat16 sm[];
    const uint32_t smb = smem_u32(sm);

    const int tid  = threadIdx.x;
    const int wid  = tid >> 5, lane = tid & 31;
    const int bh   = blockIdx.y;
    const int q0   = blockIdx.x * AQ;
    const int qrow0 = q0 + 32 * wid;

    const size_t bhS = (size_t)bh * S_;

    auto load_q = [&]() {
        #pragma unroll
        for (int i = 0; i < 24; i++) {
            int idx = tid + i * 128;
            int row = idx / 24, c = idx % 24;
            CP_ASYNC16(smb + (uint32_t)(QS_OFF + row * QSTR + c * 8) * 2,
                       Qp + (bhS + q0 + row) * AKP_ + c * 8);
        }
    };
    auto load_kv = [&](int stage, int kt) {
        int s0 = kt * AK;
        #pragma unroll
        for (int i = 0; i < 6; i++) {
            int idx = tid + i * 128;
            int row = idx / 24, c = idx % 24;
            CP_ASYNC16(smb + (uint32_t)(KS_OFF + stage * KS_STAGE + row * QSTR + c * 8) * 2,
                       Kp + (bhS + s0 + row) * AKP_ + c * 8);
        }
        #pragma unroll
        for (int i = 0; i < 2; i++) {
            int idx = tid + i * 128;
            int row = idx / 8, c = idx % 8;
            CP_ASYNC16(smb + (uint32_t)(VH_OFF + stage * VS_STAGE + row * VSTR + c * 8) * 2,
                       Vph + (bhS + s0 + row) * HD_ + c * 8);
            CP_ASYNC16(smb + (uint32_t)(VL_OFF + stage * VS_STAGE + row * VSTR + c * 8) * 2,
                       Vpl + (bhS + s0 + row) * HD_ + c * 8);
        }
    };

    float O[2][8][4];
    #pragma unroll
    for (int mi = 0; mi < 2; mi++)
        #pragma unroll
        for (int nd = 0; nd < 8; nd++)
            #pragma unroll
            for (int r = 0; r < 4; r++) O[mi][nd][r] = 0.f;
    float mst[2][2] = {{-CUDART_INF_F, -CUDART_INF_F}, {-CUDART_INF_F, -CUDART_INF_F}};
    float lst[2][2] = {{0.f, 0.f}, {0.f, 0.f}};

    const int ntiles = q0 / AK + 4;

    load_q();
    CP_COMMIT();
    load_kv(0, 0);
    CP_COMMIT();

    for (int kt = 0; kt < ntiles; kt++) {
        const int stage = kt & 1;
        if (kt + 1 < ntiles) {
            load_kv((kt + 1) & 1, kt + 1);
            CP_COMMIT();
            CP_WAIT1();
        } else {
            CP_WAIT0();
        }
        __syncthreads();

        const int k0g = kt * AK;
        const bool active = (k0g <= qrow0 + 31);

        if (active) {
            float c[2][4][4];
            #pragma unroll
            for (int mi = 0; mi < 2; mi++)
                #pragma unroll
                for (int ni = 0; ni < 4; ni++)
                    #pragma unroll
                    for (int r = 0; r < 4; r++) c[mi][ni][r] = 0.f;

            #pragma unroll
            for (int kc = 0; kc < 12; kc++) {
                uint32_t kb[4][2];
                #pragma unroll
                for (int t = 0; t < 2; t++) {
                    int krow = 16*t + (lane & 7) + 8*(lane >> 4);
                    int kcol = kc*16 + 8*((lane >> 3) & 1);
                    uint32_t r0, r1, r2, r3;
                    LDMATRIX_X4(r0, r1, r2, r3,
                        smb + (uint32_t)(KS_OFF + stage*KS_STAGE + krow*QSTR + kcol) * 2);
                    kb[2*t][0] = r0; kb[2*t][1] = r1;
                    kb[2*t+1][0] = r2; kb[2*t+1][1] = r3;
                }
                #pragma unroll
                for (int mi = 0; mi < 2; mi++) {
                    int qrow = 32*wid + 16*mi + (lane & 15);
                    int qcol = kc*16 + 8*(lane >> 4);
                    uint32_t a0, a1, a2, a3;
                    LDMATRIX_X4(a0, a1, a2, a3,
                        smb + (uint32_t)(QS_OFF + qrow*QSTR + qcol) * 2);
                    #pragma unroll
                    for (int ni = 0; ni < 4; ni++)
                        MMA_BF16(c[mi][ni][0], c[mi][ni][1], c[mi][ni][2], c[mi][ni][3],
                                 a0, a1, a2, a3, kb[ni][0], kb[ni][1]);
                }
            }

            if (k0g + AK - 1 > qrow0) {
                #pragma unroll
                for (int mi = 0; mi < 2; mi++)
                    #pragma unroll
                    for (int ni = 0; ni < 4; ni++)
                        #pragma unroll
                        for (int r = 0; r < 4; r++) {
                            int kk = k0g + ni*8 + 2*(lane & 3) + (r & 1);
                            int qq = qrow0 + 16*mi + (lane >> 2) + ((r >= 2) ? 8 : 0);
                            if (kk > qq) c[mi][ni][r] = -CUDART_INF_F;
                        }
            }

            #pragma unroll
            for (int mi = 0; mi < 2; mi++)
                #pragma unroll
                for (int h = 0; h < 2; h++) {
                    float mt = -CUDART_INF_F;
                    #pragma unroll
                    for (int ni = 0; ni < 4; ni++)
                        mt = fmaxf(mt, fmaxf(c[mi][ni][2*h], c[mi][ni][2*h+1]));
                    mt = fmaxf(mt, __shfl_xor_sync(0xffffffffu, mt, 1));
                    mt = fmaxf(mt, __shfl_xor_sync(0xffffffffu, mt, 2));
                    float mnew = fmaxf(mst[mi][h], mt);
                    float corr = __expf(mst[mi][h] - mnew);
                    mst[mi][h] = mnew;
                    float ls = 0.f;
                    #pragma unroll
                    for (int ni = 0; ni < 4; ni++) {
                        float p0 = __expf(c[mi][ni][2*h]   - mnew);
                        float p1 = __expf(c[mi][ni][2*h+1] - mnew);
                        c[mi][ni][2*h] = p0; c[mi][ni][2*h+1] = p1;
                        ls += p0 + p1;
                    }
                    lst[mi][h] = lst[mi][h] * corr + ls;
                    #pragma unroll
                    for (int nd = 0; nd < 8; nd++) {
                        O[mi][nd][2*h]   *= corr;
                        O[mi][nd][2*h+1] *= corr;
                    }
                }

            #pragma unroll
            for (int kc2 = 0; kc2 < 2; kc2++) {
                uint32_t ph[2][4], pl[2][4];
                #pragma unroll
                for (int mi = 0; mi < 2; mi++) {
                    pack_pair(c[mi][2*kc2][0],   c[mi][2*kc2][1],   ph[mi][0], pl[mi][0]);
                    pack_pair(c[mi][2*kc2][2],   c[mi][2*kc2][3],   ph[mi][1], pl[mi][1]);
                    pack_pair(c[mi][2*kc2+1][0], c[mi][2*kc2+1][1], ph[mi][2], pl[mi][2]);
                    pack_pair(c[mi][2*kc2+1][2], c[mi][2*kc2+1][3], ph[mi][3], pl[mi][3]);
                }
                uint32_t vh[8][2], vl[8][2];
                #pragma unroll
                for (int t = 0; t < 4; t++) {
                    int vrow = kc2*16 + (lane & 15);
                    int vcol = 16*t + 8*(lane >> 4);
                    uint32_t r0, r1, r2, r3;
                    LDMATRIX_X4_T(r0, r1, r2, r3,
                        smb + (uint32_t)(VH_OFF + stage*VS_STAGE + vrow*VSTR + vcol) * 2);
                    vh[2*t][0] = r0; vh[2*t][1] = r1;
                    vh[2*t+1][0] = r2; vh[2*t+1][1] = r3;
                    LDMATRIX_X4_T(r0, r1, r2, r3,
                        smb + (uint32_t)(VL_OFF + stage*VS_STAGE + vrow*VSTR + vcol) * 2);
                    vl[2*t][0] = r0; vl[2*t][1] = r1;
                    vl[2*t+1][0] = r2; vl[2*t+1][1] = r3;
                }
                #pragma unroll
                for (int mi = 0; mi < 2; mi++)
                    #pragma unroll
                    for (int nd = 0; nd < 8; nd++) {
                        MMA_BF16(O[mi][nd][0], O[mi][nd][1], O[mi][nd][2], O[mi][nd][3],
                                 ph[mi][0], ph[mi][1], ph[mi][2], ph[mi][3],
                                 vh[nd][0], vh[nd][1]);
                        MMA_BF16(O[mi][nd][0], O[mi][nd][1], O[mi][nd][2], O[mi][nd][3],
                                 ph[mi][0], ph[mi][1], ph[mi][2], ph[mi][3],
                                 vl[nd][0], vl[nd][1]);
                        MMA_BF16(O[mi][nd][0], O[mi][nd][1], O[mi][nd][2], O[mi][nd][3],
                                 pl[mi][0], pl[mi][1], pl[mi][2], pl[mi][3],
                                 vh[nd][0], vh[nd][1]);
                    }
            }
        }
        __syncthreads();
    }

    // ---- normalize + write fp16 2-term A' rows (fused split for out-proj) ----
    const int b = bh >> 4, hh = bh & 15;
    #pragma unroll
    for (int mi = 0; mi < 2; mi++)
        #pragma unroll
        for (int h = 0; h < 2; h++) {
            float lt = lst[mi][h];
            lt += __shfl_xor_sync(0xffffffffu, lt, 1);
            lt += __shfl_xor_sync(0xffffffffu, lt, 2);
            float inv = 1.f / lt;
            int row = qrow0 + 16*mi + (lane >> 2) + ((h) ? 8 : 0);
            size_t rbase = ((size_t)b*S_ + row) * KP2_;
            #pragma unroll
            for (int nd = 0; nd < 8; nd++) {
                int col = hh * HD_ + nd*8 + 2*(lane & 3);
                uint32_t phi, plo;
                pack_pair_h(O[mi][nd][2*h] * inv, O[mi][nd][2*h+1] * inv, phi, plo);
                *(uint32_t*)&Aout[rbase + col]      = phi;
                *(uint32_t*)&Aout[rbase + D_ + col] = plo;
            }
        }
}

// ============================================================================
// Launch
// ============================================================================
extern "C" void kernel_launch(void* const* d_in, const int* in_sizes, int n_in,
                              void* d_out, int out_size)
{
    const float* query = (const float*)d_in[0];
    const float* sin_q = (const float*)d_in[1];
    const float* cos_q = (const float*)d_in[2];
    const float* sin_k = (const float*)d_in[3];
    const float* cos_k = (const float*)d_in[4];
    const float* w_in  = (const float*)d_in[5];
    const float* w_out = (const float*)d_in[6];
    float* out = (float*)d_out;

    float *qkv;
    __half *Abig, *W1big, *W2big;
    __nv_bfloat16 *Qp, *Kp, *Vph, *Vpl;
    cudaGetSymbolAddress((void**)&qkv,   g_qkv);
    cudaGetSymbolAddress((void**)&Abig,  g_Abig);
    cudaGetSymbolAddress((void**)&W1big, g_W1big);
    cudaGetSymbolAddress((void**)&W2big, g_W2big);
    cudaGetSymbolAddress((void**)&Qp,    g_Qp);
    cudaGetSymbolAddress((void**)&Kp,    g_Kp);
    cudaGetSymbolAddress((void**)&Vph,   g_Vph);
    cudaGetSymbolAddress((void**)&Vpl,   g_Vpl);

    static bool attr_set = false;
    if (!attr_set) {
        cudaFuncSetAttribute(attn_mma_kernel,
                             cudaFuncAttributeMaxDynamicSharedMemorySize, ATTN_SMEM_BYTES);
        attr_set = true;
    }

    const int M = B_ * S_;   // 4096

    // Prep: fp16 2-term encode
    split_a_kernel<<<(M*D_ + 255)/256, 256>>>(query, Abig, M*D_);
    transpose_split_w_kernel<<<dim3(3*D_/32, D_/32), dim3(32,8)>>>(w_in,  W1big, 3*D_);
    transpose_split_w_kernel<<<dim3(D_/32,   D_/32), dim3(32,8)>>>(w_out, W2big, D_);

    // 1) QKV projection (fp16 tensor cores, K'=2048)
    gemm_mma_kernel<<<dim3(3*D_/GBN, M/GBM), 256>>>(Abig, W1big, qkv, M, 3*D_);

    // 2) RoPE + pack tensor operands (bf16 3-term, unchanged)
    rope_pack_kernel<<<(B_*S_*D_ + 255)/256, 256>>>(
        qkv, sin_q, cos_q, sin_k, cos_k, Qp, Kp, Vph, Vpl);

    // 3) Tensor-core causal flash attention (writes fp16 A' directly)
    attn_mma_kernel<<<dim3(S_/AQ, B_*H_), 128, ATTN_SMEM_BYTES>>>(Qp, Kp, Vph, Vpl, Abig);

    // 4) Output projection (fp16 tensor cores, K'=2048)
    gemm_mma_kernel<<<dim3(D_/GBN, M/GBM), 256>>>(Abig, W2big, out, M, D_);
}

// round 7
// speedup vs baseline: 1.5150x; 1.1685x over previous
#include <cuda_runtime.h>
#include <cuda_fp16.h>
#include <math_constants.h>
#include <cstdint>

// Problem constants
#define B_   2
#define S_   2048
#define D_   1024
#define H_   16
#define HD_  64
#define SCALE_ 0.125f   // 1/sqrt(64)
#define KP2_ (2 * D_)   // fp16 2-term K' = 2048 for projections
#define AKP_ 128        // fp16 2-term K' for QK^T (2*64)

// ============================================================================
// Static device scratch
// ============================================================================
__device__ float g_qkv [(size_t)(B_*S_) * (3*D_)];
__device__ __half g_Abig [(size_t)(B_*S_) * KP2_];      // [4096, 2048] fp16
__device__ __half g_W1big[(size_t)(3*D_) * KP2_];       // [3072, 2048] fp16
__device__ __half g_W2big[(size_t)D_ * KP2_];           // [1024, 2048] fp16
__device__ __half g_Qp [(size_t)B_*H_*S_*AKP_];         // [Qh|Ql], scale folded
__device__ __half g_Kp [(size_t)B_*H_*S_*AKP_];         // [Kh|Kh]
__device__ __half g_Vph[(size_t)B_*H_*S_*HD_];          // fp16(V)

// ============================================================================
// PTX helpers (sm_80-era only — safe for compute_103 baseline PTX)
// ============================================================================
__device__ __forceinline__ uint32_t smem_u32(const void* p) {
    uint32_t a;
    asm("{ .reg .u64 t; cvta.to.shared.u64 t, %1; cvt.u32.u64 %0, t; }" : "=r"(a) : "l"(p));
    return a;
}
#define CP_ASYNC16(saddr, gptr) \
    asm volatile("cp.async.cg.shared.global [%0], [%1], 16;" :: "r"(saddr), "l"(gptr))
#define CP_COMMIT() asm volatile("cp.async.commit_group;" ::: "memory")
#define CP_WAIT1()  asm volatile("cp.async.wait_group 1;" ::: "memory")
#define CP_WAIT0()  asm volatile("cp.async.wait_group 0;" ::: "memory")
#define LDMATRIX_X4(r0, r1, r2, r3, addr) \
    asm volatile("ldmatrix.sync.aligned.m8n8.x4.shared.b16 {%0,%1,%2,%3}, [%4];" \
        : "=r"(r0), "=r"(r1), "=r"(r2), "=r"(r3) : "r"(addr))
#define LDMATRIX_X4_T(r0, r1, r2, r3, addr) \
    asm volatile("ldmatrix.sync.aligned.m8n8.x4.trans.shared.b16 {%0,%1,%2,%3}, [%4];" \
        : "=r"(r0), "=r"(r1), "=r"(r2), "=r"(r3) : "r"(addr))
#define MMA_F16(c0, c1, c2, c3, a0, a1, a2, a3, b0, b1) \
    asm volatile("mma.sync.aligned.m16n8k16.row.col.f32.f16.f16.f32 " \
        "{%0,%1,%2,%3}, {%4,%5,%6,%7}, {%8,%9}, {%0,%1,%2,%3};" \
        : "+f"(c0), "+f"(c1), "+f"(c2), "+f"(c3) \
        : "r"(a0), "r"(a1), "r"(a2), "r"(a3), "r"(b0), "r"(b1))

// fp16 hi/lo pack
__device__ __forceinline__ void pack_pair_h(float p0, float p1, uint32_t &h, uint32_t &l) {
    __half h0 = __float2half_rn(p0), h1 = __float2half_rn(p1);
    float r0 = p0 - __half2float(h0);
    float r1 = p1 - __half2float(h1);
    __half l0 = __float2half_rn(r0), l1 = __float2half_rn(r1);
    h = ((uint32_t)__half_as_ushort(h1) << 16) | (uint32_t)__half_as_ushort(h0);
    l = ((uint32_t)__half_as_ushort(l1) << 16) | (uint32_t)__half_as_ushort(l0);
}

// ============================================================================
// Prep: fp16 2-term encode for projections (unchanged from R6)
// ============================================================================
__global__ __launch_bounds__(256) void split_a_kernel(
    const float* __restrict__ x, __half* __restrict__ out, int total)
{
    int i = blockIdx.x * blockDim.x + threadIdx.x;
    if (i >= total) return;
    int r = i >> 10, c = i & (D_ - 1);
    float v = x[i];
    __half h = __float2half_rn(v);
    __half l = __float2half_rn(v - __half2float(h));
    size_t base = (size_t)r * KP2_;
    out[base + c]      = h;
    out[base + D_ + c] = l;
}

__global__ __launch_bounds__(256) void transpose_split_w_kernel(
    const float* __restrict__ w, __half* __restrict__ out, int N)
{
    __shared__ float tile[32][33];
    int k0 = blockIdx.y * 32, n0 = blockIdx.x * 32;
    int tx = threadIdx.x, ty = threadIdx.y;
    #pragma unroll
    for (int i = 0; i < 32; i += 8)
        tile[ty + i][tx] = w[(size_t)(k0 + ty + i) * N + n0 + tx];
    __syncthreads();
    #pragma unroll
    for (int i = 0; i < 32; i += 8) {
        float x = tile[tx][ty + i];
        __half h = __float2half_rn(x);
        size_t o = (size_t)(n0 + ty + i) * KP2_ + k0 + tx;
        out[o]      = h;
        out[o + D_] = h;
    }
}

// ============================================================================
// fp16 mma.sync GEMM (unchanged from R6 — known-good)
// ============================================================================
#define GBM 128
#define GBN 128
#define GBK 32
#define SSTRIDE 40

__global__ __launch_bounds__(256) void gemm_mma_kernel(
    const __half* __restrict__ A,
    const __half* __restrict__ W,
    float* __restrict__ C, int M, int N)
{
    __shared__ __half As[2][GBM * SSTRIDE];
    __shared__ __half Bs[2][GBN * SSTRIDE];

    const int tid  = threadIdx.x;
    const int wid  = tid >> 5, lane = tid & 31;
    const int m0   = blockIdx.y * GBM;
    const int n0   = blockIdx.x * GBN;
    const int wm   = wid >> 2;
    const int wn   = wid & 3;

    float acc[4][4][4];
    #pragma unroll
    for (int mi = 0; mi < 4; mi++)
        #pragma unroll
        for (int ni = 0; ni < 4; ni++)
            #pragma unroll
            for (int r = 0; r < 4; r++) acc[mi][ni][r] = 0.f;

    const uint32_t as0 = smem_u32(&As[0][0]), as1 = smem_u32(&As[1][0]);
    const uint32_t bs0 = smem_u32(&Bs[0][0]), bs1 = smem_u32(&Bs[1][0]);

    const int lr0 = tid >> 2,          lc0 = (tid & 3);
    const int lr1 = (tid + 256) >> 2,  lc1 = (tid & 3);

    auto load_stage = [&](int stage, int kb) {
        const int kt = kb * GBK;
        const uint32_t as = stage ? as1 : as0;
        const uint32_t bs = stage ? bs1 : bs0;
        CP_ASYNC16(as + (uint32_t)(lr0 * SSTRIDE + lc0 * 8) * 2,
                   A + (size_t)(m0 + lr0) * KP2_ + kt + lc0 * 8);
        CP_ASYNC16(as + (uint32_t)(lr1 * SSTRIDE + lc1 * 8) * 2,
                   A + (size_t)(m0 + lr1) * KP2_ + kt + lc1 * 8);
        CP_ASYNC16(bs + (uint32_t)(lr0 * SSTRIDE + lc0 * 8) * 2,
                   W + (size_t)(n0 + lr0) * KP2_ + kt + lc0 * 8);
        CP_ASYNC16(bs + (uint32_t)(lr1 * SSTRIDE + lc1 * 8) * 2,
                   W + (size_t)(n0 + lr1) * KP2_ + kt + lc1 * 8);
    };

    const int NKB = KP2_ / GBK;   // 64
    load_stage(0, 0);
    CP_COMMIT();

    for (int kb = 0; kb < NKB; kb++) {
        if (kb + 1 < NKB) {
            load_stage((kb + 1) & 1, kb + 1);
            CP_COMMIT();
            CP_WAIT1();
        } else {
            CP_WAIT0();
        }
        __syncthreads();

        const uint32_t as = (kb & 1) ? as1 : as0;
        const uint32_t bs = (kb & 1) ? bs1 : bs0;

        #pragma unroll
        for (int ks = 0; ks < 2; ks++) {
            uint32_t a[4][4];
            #pragma unroll
            for (int mi = 0; mi < 4; mi++) {
                int row = wm * 64 + mi * 16 + (lane & 15);
                int col = ks * 16 + (lane >> 4) * 8;
                LDMATRIX_X4(a[mi][0], a[mi][1], a[mi][2], a[mi][3],
                            as + (uint32_t)(row * SSTRIDE + col) * 2);
            }
            uint32_t b[4][2];
            #pragma unroll
            for (int nb = 0; nb < 2; nb++) {
                int nrow = wn * 32 + nb * 16 + ((lane & 16) ? 8 : 0) + (lane & 7);
                int kcol = ks * 16 + ((lane & 8) ? 8 : 0);
                uint32_t r0, r1, r2, r3;
                LDMATRIX_X4(r0, r1, r2, r3,
                            bs + (uint32_t)(nrow * SSTRIDE + kcol) * 2);
                b[nb*2][0] = r0; b[nb*2][1] = r1;
                b[nb*2+1][0] = r2; b[nb*2+1][1] = r3;
            }
            #pragma unroll
            for (int mi = 0; mi < 4; mi++)
                #pragma unroll
                for (int ni = 0; ni < 4; ni++)
                    MMA_F16(acc[mi][ni][0], acc[mi][ni][1], acc[mi][ni][2], acc[mi][ni][3],
                            a[mi][0], a[mi][1], a[mi][2], a[mi][3],
                            b[ni][0], b[ni][1]);
        }
        __syncthreads();
    }

    #pragma unroll
    for (int mi = 0; mi < 4; mi++) {
        int mrow = m0 + wm * 64 + mi * 16 + (lane >> 2);
        #pragma unroll
        for (int ni = 0; ni < 4; ni++) {
            int ncol = n0 + wn * 32 + ni * 8 + (lane & 3) * 2;
            *(float2*)&C[(size_t)mrow * N + ncol] =
                make_float2(acc[mi][ni][0], acc[mi][ni][1]);
            *(float2*)&C[(size_t)(mrow + 8) * N + ncol] =
                make_float2(acc[mi][ni][2], acc[mi][ni][3]);
        }
    }
}

// ============================================================================
// RoPE -> fp16 2-term attention operands.
// Qp row: [ fp16(scale*rope(q)) hi | lo ]   (exact Q)
// Kp row: [ fp16(rope(k)) | fp16(rope(k)) ] (single K rounding)
// Vph: fp16(v)
// ============================================================================
__global__ __launch_bounds__(256) void rope_pack_kernel(
    const float* __restrict__ qkv,
    const float* __restrict__ sin_q, const float* __restrict__ cos_q,
    const float* __restrict__ sin_k, const float* __restrict__ cos_k,
    __half* __restrict__ Qp, __half* __restrict__ Kp, __half* __restrict__ Vph)
{
    int idx = blockIdx.x * blockDim.x + threadIdx.x;
    if (idx >= B_*S_*D_) return;
    int d = idx % HD_;
    int h = (idx / HD_) % H_;
    int s = (idx / D_) % S_;
    int b = idx / (S_ * D_);

    const float* row = qkv + ((size_t)b*S_ + s) * (3*D_);
    int hd = h*HD_ + d;
    int dp = (d < HD_/2) ? d + HD_/2 : d - HD_/2;
    float sgn = (d < HD_/2) ? -1.f : 1.f;

    float qv = row[hd];
    float kv = row[D_ + hd];
    float vv = row[2*D_ + hd];
    float qp = row[h*HD_ + dp];
    float kp = row[D_ + h*HD_ + dp];

    float sq = sin_q[s*HD_ + d], cq = cos_q[s*HD_ + d];
    float sk = sin_k[s*HD_ + d], ck = cos_k[s*HD_ + d];

    float qr = (qv * cq + sgn * qp * sq) * SCALE_;
    float kr = kv * ck + sgn * kp * sk;

    size_t bhs = ((size_t)(b*H_ + h) * S_ + s);

    __half qh = __float2half_rn(qr);
    __half ql = __float2half_rn(qr - __half2float(qh));
    __half kh = __float2half_rn(kr);

    __half* qrow = Qp + bhs * AKP_;
    qrow[d] = qh; qrow[64 + d] = ql;
    __half* krow = Kp + bhs * AKP_;
    krow[d] = kh; krow[64 + d] = kh;
    Vph[bhs * HD_ + d] = __float2half_rn(vv);
}

// ============================================================================
// Tensor-core causal flash attention, fp16 2-term compensated.
// CTA: 128 queries x one (b,h), 4 warps x 32 rows, 32-key tiles, 2-stage
// cp.async. QK: exact-Q x fp16(K) via K'=128. PV: exact-P x fp16(V) via
// in-register P hi/lo split (2 MMAs). Epilogue writes fp16 2-term A'.
// ============================================================================
#define AQ 128
#define AK 32
#define QSTR 136   // halves per Q/K smem row (128 + 8 pad)
#define VSTR 72    // halves per V smem row (64 + 8 pad)

#define QS_OFF   0
#define KS_OFF   17408           // 128*136
#define KS_STAGE 4352            // 32*136
#define VH_OFF   26112           // KS_OFF + 2*KS_STAGE
#define VS_STAGE 2304            // 32*72
#define ATTN_SMEM_BYTES ((VH_OFF + 2*VS_STAGE) * 2)   // 61440

__global__ __launch_bounds__(128) void attn_mma_kernel(
    const __half* __restrict__ Qp, const __half* __restrict__ Kp,
    const __half* __restrict__ Vph,
    __half* __restrict__ Aout)   // [B*S, KP2] fp16 2-term encoded
{
    extern __shared__ __align__(16) __half sm[];
    const uint32_t smb = smem_u32(sm);

    const int tid  = threadIdx.x;
    const int wid  = tid >> 5, lane = tid & 31;
    const int bh   = blockIdx.y;
    const int q0   = blockIdx.x * AQ;
    const int qrow0 = q0 + 32 * wid;

    const size_t bhS = (size_t)bh * S_;

    auto load_q = [&]() {
        #pragma unroll
        for (int i = 0; i < 16; i++) {           // 128 rows x 16 float4
            int idx = tid + i * 128;
            int row = idx >> 4, c = idx & 15;
            CP_ASYNC16(smb + (uint32_t)(QS_OFF + row * QSTR + c * 8) * 2,
                       Qp + (bhS + q0 + row) * AKP_ + c * 8);
        }
    };
    auto load_kv = [&](int stage, int kt) {
        int s0 = kt * AK;
        #pragma unroll
        for (int i = 0; i < 4; i++) {            // 32 rows x 16 float4
            int idx = tid + i * 128;
            int row = idx >> 4, c = idx & 15;
            CP_ASYNC16(smb + (uint32_t)(KS_OFF + stage * KS_STAGE + row * QSTR + c * 8) * 2,
                       Kp + (bhS + s0 + row) * AKP_ + c * 8);
        }
        #pragma unroll
        for (int i = 0; i < 2; i++) {            // 32 rows x 8 float4
            int idx = tid + i * 128;
            int row = idx >> 3, c = idx & 7;
            CP_ASYNC16(smb + (uint32_t)(VH_OFF + stage * VS_STAGE + row * VSTR + c * 8) * 2,
                       Vph + (bhS + s0 + row) * HD_ + c * 8);
        }
    };

    float O[2][8][4];
    #pragma unroll
    for (int mi = 0; mi < 2; mi++)
        #pragma unroll
        for (int nd = 0; nd < 8; nd++)
            #pragma unroll
            for (int r = 0; r < 4; r++) O[mi][nd][r] = 0.f;
    float mst[2][2] = {{-CUDART_INF_F, -CUDART_INF_F}, {-CUDART_INF_F, -CUDART_INF_F}};
    float lst[2][2] = {{0.f, 0.f}, {0.f, 0.f}};

    const int ntiles = q0 / AK + 4;

    load_q();
    CP_COMMIT();
    load_kv(0, 0);
    CP_COMMIT();

    for (int kt = 0; kt < ntiles; kt++) {
        const int stage = kt & 1;
        if (kt + 1 < ntiles) {
            load_kv((kt + 1) & 1, kt + 1);
            CP_COMMIT();
            CP_WAIT1();
        } else {
            CP_WAIT0();
        }
        __syncthreads();

        const int k0g = kt * AK;
        const bool active = (k0g <= qrow0 + 31);

        if (active) {
            float c[2][4][4];
            #pragma unroll
            for (int mi = 0; mi < 2; mi++)
                #pragma unroll
                for (int ni = 0; ni < 4; ni++)
                    #pragma unroll
                    for (int r = 0; r < 4; r++) c[mi][ni][r] = 0.f;

            #pragma unroll
            for (int kc = 0; kc < 8; kc++) {     // K'=128 -> 8 k16 chunks
                uint32_t kb[4][2];
                #pragma unroll
                for (int t = 0; t < 2; t++) {
                    int krow = 16*t + (lane & 7) + 8*(lane >> 4);
                    int kcol = kc*16 + 8*((lane >> 3) & 1);
                    uint32_t r0, r1, r2, r3;
                    LDMATRIX_X4(r0, r1, r2, r3,
                        smb + (uint32_t)(KS_OFF + stage*KS_STAGE + krow*QSTR + kcol) * 2);
                    kb[2*t][0] = r0; kb[2*t][1] = r1;
                    kb[2*t+1][0] = r2; kb[2*t+1][1] = r3;
                }
                #pragma unroll
                for (int mi = 0; mi < 2; mi++) {
                    int qrow = 32*wid + 16*mi + (lane & 15);
                    int qcol = kc*16 + 8*(lane >> 4);
                    uint32_t a0, a1, a2, a3;
                    LDMATRIX_X4(a0, a1, a2, a3,
                        smb + (uint32_t)(QS_OFF + qrow*QSTR + qcol) * 2);
                    #pragma unroll
                    for (int ni = 0; ni < 4; ni++)
                        MMA_F16(c[mi][ni][0], c[mi][ni][1], c[mi][ni][2], c[mi][ni][3],
                                a0, a1, a2, a3, kb[ni][0], kb[ni][1]);
                }
            }

            if (k0g + AK - 1 > qrow0) {
                #pragma unroll
                for (int mi = 0; mi < 2; mi++)
                    #pragma unroll
                    for (int ni = 0; ni < 4; ni++)
                        #pragma unroll
                        for (int r = 0; r < 4; r++) {
                            int kk = k0g + ni*8 + 2*(lane & 3) + (r & 1);
                            int qq = qrow0 + 16*mi + (lane >> 2) + ((r >= 2) ? 8 : 0);
                            if (kk > qq) c[mi][ni][r] = -CUDART_INF_F;
                        }
            }

            #pragma unroll
            for (int mi = 0; mi < 2; mi++)
                #pragma unroll
                for (int h = 0; h < 2; h++) {
                    float mt = -CUDART_INF_F;
                    #pragma unroll
                    for (int ni = 0; ni < 4; ni++)
                        mt = fmaxf(mt, fmaxf(c[mi][ni][2*h], c[mi][ni][2*h+1]));
                    mt = fmaxf(mt, __shfl_xor_sync(0xffffffffu, mt, 1));
                    mt = fmaxf(mt, __shfl_xor_sync(0xffffffffu, mt, 2));
                    float mnew = fmaxf(mst[mi][h], mt);
                    float corr = __expf(mst[mi][h] - mnew);
                    mst[mi][h] = mnew;
                    float ls = 0.f;
                    #pragma unroll
                    for (int ni = 0; ni < 4; ni++) {
                        float p0 = __expf(c[mi][ni][2*h]   - mnew);
                        float p1 = __expf(c[mi][ni][2*h+1] - mnew);
                        c[mi][ni][2*h] = p0; c[mi][ni][2*h+1] = p1;
                        ls += p0 + p1;
                    }
                    lst[mi][h] = lst[mi][h] * corr + ls;
                    #pragma unroll
                    for (int nd = 0; nd < 8; nd++) {
                        O[mi][nd][2*h]   *= corr;
                        O[mi][nd][2*h+1] *= corr;
                    }
                }

            // ---- PV: (Ph + Pl) x fp16(V), 2 MMAs ----
            #pragma unroll
            for (int kc2 = 0; kc2 < 2; kc2++) {
                uint32_t ph[2][4], pl[2][4];
                #pragma unroll
                for (int mi = 0; mi < 2; mi++) {
                    pack_pair_h(c[mi][2*kc2][0],   c[mi][2*kc2][1],   ph[mi][0], pl[mi][0]);
                    pack_pair_h(c[mi][2*kc2][2],   c[mi][2*kc2][3],   ph[mi][1], pl[mi][1]);
                    pack_pair_h(c[mi][2*kc2+1][0], c[mi][2*kc2+1][1], ph[mi][2], pl[mi][2]);
                    pack_pair_h(c[mi][2*kc2+1][2], c[mi][2*kc2+1][3], ph[mi][3], pl[mi][3]);
                }
                uint32_t vh[8][2];
                #pragma unroll
                for (int t = 0; t < 4; t++) {
                    int vrow = kc2*16 + (lane & 15);
                    int vcol = 16*t + 8*(lane >> 4);
                    uint32_t r0, r1, r2, r3;
                    LDMATRIX_X4_T(r0, r1, r2, r3,
                        smb + (uint32_t)(VH_OFF + stage*VS_STAGE + vrow*VSTR + vcol) * 2);
                    vh[2*t][0] = r0; vh[2*t][1] = r1;
                    vh[2*t+1][0] = r2; vh[2*t+1][1] = r3;
                }
                #pragma unroll
                for (int mi = 0; mi < 2; mi++)
                    #pragma unroll
                    for (int nd = 0; nd < 8; nd++) {
                        MMA_F16(O[mi][nd][0], O[mi][nd][1], O[mi][nd][2], O[mi][nd][3],
                                ph[mi][0], ph[mi][1], ph[mi][2], ph[mi][3],
                                vh[nd][0], vh[nd][1]);
                        MMA_F16(O[mi][nd][0], O[mi][nd][1], O[mi][nd][2], O[mi][nd][3],
                                pl[mi][0], pl[mi][1], pl[mi][2], pl[mi][3],
                                vh[nd][0], vh[nd][1]);
                    }
            }
        }
        __syncthreads();
    }

    // ---- normalize + write fp16 2-term A' rows (fused split for out-proj) ----
    const int b = bh >> 4, hh = bh & 15;
    #pragma unroll
    for (int mi = 0; mi < 2; mi++)
        #pragma unroll
        for (int h = 0; h < 2; h++) {
            float lt = lst[mi][h];
            lt += __shfl_xor_sync(0xffffffffu, lt, 1);
            lt += __shfl_xor_sync(0xffffffffu, lt, 2);
            float inv = 1.f / lt;
            int row = qrow0 + 16*mi + (lane >> 2) + ((h) ? 8 : 0);
            size_t rbase = ((size_t)b*S_ + row) * KP2_;
            #pragma unroll
            for (int nd = 0; nd < 8; nd++) {
                int col = hh * HD_ + nd*8 + 2*(lane & 3);
                uint32_t phi, plo;
                pack_pair_h(O[mi][nd][2*h] * inv, O[mi][nd][2*h+1] * inv, phi, plo);
                *(uint32_t*)&Aout[rbase + col]      = phi;
                *(uint32_t*)&Aout[rbase + D_ + col] = plo;
            }
        }
}

// ============================================================================
// Launch
// ============================================================================
extern "C" void kernel_launch(void* const* d_in, const int* in_sizes, int n_in,
                              void* d_out, int out_size)
{
    const float* query = (const float*)d_in[0];
    const float* sin_q = (const float*)d_in[1];
    const float* cos_q = (const float*)d_in[2];
    const float* sin_k = (const float*)d_in[3];
    const float* cos_k = (const float*)d_in[4];
    const float* w_in  = (const float*)d_in[5];
    const float* w_out = (const float*)d_in[6];
    float* out = (float*)d_out;

    float *qkv;
    __half *Abig, *W1big, *W2big, *Qp, *Kp, *Vph;
    cudaGetSymbolAddress((void**)&qkv,   g_qkv);
    cudaGetSymbolAddress((void**)&Abig,  g_Abig);
    cudaGetSymbolAddress((void**)&W1big, g_W1big);
    cudaGetSymbolAddress((void**)&W2big, g_W2big);
    cudaGetSymbolAddress((void**)&Qp,    g_Qp);
    cudaGetSymbolAddress((void**)&Kp,    g_Kp);
    cudaGetSymbolAddress((void**)&Vph,   g_Vph);

    static bool attr_set = false;
    if (!attr_set) {
        cudaFuncSetAttribute(attn_mma_kernel,
                             cudaFuncAttributeMaxDynamicSharedMemorySize, ATTN_SMEM_BYTES);
        attr_set = true;
    }

    const int M = B_ * S_;   // 4096

    // Prep: fp16 2-term encode
    split_a_kernel<<<(M*D_ + 255)/256, 256>>>(query, Abig, M*D_);
    transpose_split_w_kernel<<<dim3(3*D_/32, D_/32), dim3(32,8)>>>(w_in,  W1big, 3*D_);
    transpose_split_w_kernel<<<dim3(D_/32,   D_/32), dim3(32,8)>>>(w_out, W2big, D_);

    // 1) QKV projection (fp16 tensor cores, K'=2048)
    gemm_mma_kernel<<<dim3(3*D_/GBN, M/GBM), 256>>>(Abig, W1big, qkv, M, 3*D_);

    // 2) RoPE + pack fp16 2-term attention operands
    rope_pack_kernel<<<(B_*S_*D_ + 255)/256, 256>>>(
        qkv, sin_q, cos_q, sin_k, cos_k, Qp, Kp, Vph);

    // 3) Tensor-core causal flash attention (fp16 2-term; writes A' directly)
    attn_mma_kernel<<<dim3(S_/AQ, B_*H_), 128, ATTN_SMEM_BYTES>>>(Qp, Kp, Vph, Abig);

    // 4) Output projection (fp16 tensor cores, K'=2048)
    gemm_mma_kernel<<<dim3(D_/GBN, M/GBM), 256>>>(Abig, W2big, out, M, D_);
}

// round 8
// speedup vs baseline: 2.0752x; 1.3697x over previous
#include <cuda_runtime.h>
#include <cuda_fp16.h>
#include <math_constants.h>
#include <cstdint>

// Problem constants
#define B_   2
#define S_   2048
#define D_   1024
#define H_   16
#define HD_  64
#define SCALE_ 0.125f   // 1/sqrt(64)
#define KPG_ D_         // plain fp16 GEMM K = 1024
#define AKP_ 128        // fp16 2-term K' for QK^T (2*64)

// ============================================================================
// Static device scratch
// ============================================================================
__device__ float g_qkv [(size_t)(B_*S_) * (3*D_)];
__device__ __half g_A   [(size_t)(B_*S_) * D_];         // [4096, 1024] fp16
__device__ __half g_W1t [(size_t)(3*D_) * D_];          // [3072, 1024] fp16 (N-major)
__device__ __half g_W2t [(size_t)D_ * D_];              // [1024, 1024] fp16 (N-major)
__device__ __half g_Qp [(size_t)B_*H_*S_*AKP_];         // [Qh|Ql], scale folded
__device__ __half g_Kp [(size_t)B_*H_*S_*AKP_];         // [Kh|Kh]
__device__ __half g_Vph[(size_t)B_*H_*S_*HD_];          // fp16(V)

// ============================================================================
// PTX helpers (sm_80-era only — safe for compute_103 baseline PTX)
// ============================================================================
__device__ __forceinline__ uint32_t smem_u32(const void* p) {
    uint32_t a;
    asm("{ .reg .u64 t; cvta.to.shared.u64 t, %1; cvt.u32.u64 %0, t; }" : "=r"(a) : "l"(p));
    return a;
}
#define CP_ASYNC16(saddr, gptr) \
    asm volatile("cp.async.cg.shared.global [%0], [%1], 16;" :: "r"(saddr), "l"(gptr))
#define CP_COMMIT() asm volatile("cp.async.commit_group;" ::: "memory")
#define CP_WAIT1()  asm volatile("cp.async.wait_group 1;" ::: "memory")
#define CP_WAIT0()  asm volatile("cp.async.wait_group 0;" ::: "memory")
#define LDMATRIX_X4(r0, r1, r2, r3, addr) \
    asm volatile("ldmatrix.sync.aligned.m8n8.x4.shared.b16 {%0,%1,%2,%3}, [%4];" \
        : "=r"(r0), "=r"(r1), "=r"(r2), "=r"(r3) : "r"(addr))
#define LDMATRIX_X4_T(r0, r1, r2, r3, addr) \
    asm volatile("ldmatrix.sync.aligned.m8n8.x4.trans.shared.b16 {%0,%1,%2,%3}, [%4];" \
        : "=r"(r0), "=r"(r1), "=r"(r2), "=r"(r3) : "r"(addr))
#define MMA_F16(c0, c1, c2, c3, a0, a1, a2, a3, b0, b1) \
    asm volatile("mma.sync.aligned.m16n8k16.row.col.f32.f16.f16.f32 " \
        "{%0,%1,%2,%3}, {%4,%5,%6,%7}, {%8,%9}, {%0,%1,%2,%3};" \
        : "+f"(c0), "+f"(c1), "+f"(c2), "+f"(c3) \
        : "r"(a0), "r"(a1), "r"(a2), "r"(a3), "r"(b0), "r"(b1))

// fp16 hi/lo pack
__device__ __forceinline__ void pack_pair_h(float p0, float p1, uint32_t &h, uint32_t &l) {
    __half h0 = __float2half_rn(p0), h1 = __float2half_rn(p1);
    float r0 = p0 - __half2float(h0);
    float r1 = p1 - __half2float(h1);
    __half l0 = __float2half_rn(r0), l1 = __float2half_rn(r1);
    h = ((uint32_t)__half_as_ushort(h1) << 16) | (uint32_t)__half_as_ushort(h0);
    l = ((uint32_t)__half_as_ushort(l1) << 16) | (uint32_t)__half_as_ushort(l0);
}
__device__ __forceinline__ uint32_t pack2h(float p0, float p1) {
    __half h0 = __float2half_rn(p0), h1 = __float2half_rn(p1);
    return ((uint32_t)__half_as_ushort(h1) << 16) | (uint32_t)__half_as_ushort(h0);
}

// ============================================================================
// Prep: plain fp16 casts
// ============================================================================
__global__ __launch_bounds__(256) void cast_a_kernel(
    const float* __restrict__ x, __half* __restrict__ out, int total)
{
    int i = blockIdx.x * blockDim.x + threadIdx.x;
    if (i >= total) return;
    out[i] = __float2half_rn(x[i]);
}

// w[K=1024][N] -> out[N][1024] fp16
__global__ __launch_bounds__(256) void transpose_cast_w_kernel(
    const float* __restrict__ w, __half* __restrict__ out, int N)
{
    __shared__ float tile[32][33];
    int k0 = blockIdx.y * 32, n0 = blockIdx.x * 32;
    int tx = threadIdx.x, ty = threadIdx.y;
    #pragma unroll
    for (int i = 0; i < 32; i += 8)
        tile[ty + i][tx] = w[(size_t)(k0 + ty + i) * N + n0 + tx];
    __syncthreads();
    #pragma unroll
    for (int i = 0; i < 32; i += 8)
        out[(size_t)(n0 + ty + i) * KPG_ + k0 + tx] = __float2half_rn(tile[tx][ty + i]);
}

// ============================================================================
// fp16 mma.sync GEMM: C[M,N] = A[M,K] @ W[N,K]^T, K=1024, fp32 accumulate.
// R4/R6-proven structure: CTA 128x128, BK=32, 8 warps of 64x32, 2-stage.
// ============================================================================
#define GBM 128
#define GBN 128
#define GBK 32
#define SSTRIDE 40

__global__ __launch_bounds__(256) void gemm_mma_kernel(
    const __half* __restrict__ A,
    const __half* __restrict__ W,
    float* __restrict__ C, int M, int N)
{
    __shared__ __half As[2][GBM * SSTRIDE];
    __shared__ __half Bs[2][GBN * SSTRIDE];

    const int tid  = threadIdx.x;
    const int wid  = tid >> 5, lane = tid & 31;
    const int m0   = blockIdx.y * GBM;
    const int n0   = blockIdx.x * GBN;
    const int wm   = wid >> 2;
    const int wn   = wid & 3;

    float acc[4][4][4];
    #pragma unroll
    for (int mi = 0; mi < 4; mi++)
        #pragma unroll
        for (int ni = 0; ni < 4; ni++)
            #pragma unroll
            for (int r = 0; r < 4; r++) acc[mi][ni][r] = 0.f;

    const uint32_t as0 = smem_u32(&As[0][0]), as1 = smem_u32(&As[1][0]);
    const uint32_t bs0 = smem_u32(&Bs[0][0]), bs1 = smem_u32(&Bs[1][0]);

    const int lr0 = tid >> 2,          lc0 = (tid & 3);
    const int lr1 = (tid + 256) >> 2,  lc1 = (tid & 3);

    auto load_stage = [&](int stage, int kb) {
        const int kt = kb * GBK;
        const uint32_t as = stage ? as1 : as0;
        const uint32_t bs = stage ? bs1 : bs0;
        CP_ASYNC16(as + (uint32_t)(lr0 * SSTRIDE + lc0 * 8) * 2,
                   A + (size_t)(m0 + lr0) * KPG_ + kt + lc0 * 8);
        CP_ASYNC16(as + (uint32_t)(lr1 * SSTRIDE + lc1 * 8) * 2,
                   A + (size_t)(m0 + lr1) * KPG_ + kt + lc1 * 8);
        CP_ASYNC16(bs + (uint32_t)(lr0 * SSTRIDE + lc0 * 8) * 2,
                   W + (size_t)(n0 + lr0) * KPG_ + kt + lc0 * 8);
        CP_ASYNC16(bs + (uint32_t)(lr1 * SSTRIDE + lc1 * 8) * 2,
                   W + (size_t)(n0 + lr1) * KPG_ + kt + lc1 * 8);
    };

    const int NKB = KPG_ / GBK;   // 32
    load_stage(0, 0);
    CP_COMMIT();

    for (int kb = 0; kb < NKB; kb++) {
        if (kb + 1 < NKB) {
            load_stage((kb + 1) & 1, kb + 1);
            CP_COMMIT();
            CP_WAIT1();
        } else {
            CP_WAIT0();
        }
        __syncthreads();

        const uint32_t as = (kb & 1) ? as1 : as0;
        const uint32_t bs = (kb & 1) ? bs1 : bs0;

        #pragma unroll
        for (int ks = 0; ks < 2; ks++) {
            uint32_t a[4][4];
            #pragma unroll
            for (int mi = 0; mi < 4; mi++) {
                int row = wm * 64 + mi * 16 + (lane & 15);
                int col = ks * 16 + (lane >> 4) * 8;
                LDMATRIX_X4(a[mi][0], a[mi][1], a[mi][2], a[mi][3],
                            as + (uint32_t)(row * SSTRIDE + col) * 2);
            }
            uint32_t b[4][2];
            #pragma unroll
            for (int nb = 0; nb < 2; nb++) {
                int nrow = wn * 32 + nb * 16 + ((lane & 16) ? 8 : 0) + (lane & 7);
                int kcol = ks * 16 + ((lane & 8) ? 8 : 0);
                uint32_t r0, r1, r2, r3;
                LDMATRIX_X4(r0, r1, r2, r3,
                            bs + (uint32_t)(nrow * SSTRIDE + kcol) * 2);
                b[nb*2][0] = r0; b[nb*2][1] = r1;
                b[nb*2+1][0] = r2; b[nb*2+1][1] = r3;
            }
            #pragma unroll
            for (int mi = 0; mi < 4; mi++)
                #pragma unroll
                for (int ni = 0; ni < 4; ni++)
                    MMA_F16(acc[mi][ni][0], acc[mi][ni][1], acc[mi][ni][2], acc[mi][ni][3],
                            a[mi][0], a[mi][1], a[mi][2], a[mi][3],
                            b[ni][0], b[ni][1]);
        }
        __syncthreads();
    }

    #pragma unroll
    for (int mi = 0; mi < 4; mi++) {
        int mrow = m0 + wm * 64 + mi * 16 + (lane >> 2);
        #pragma unroll
        for (int ni = 0; ni < 4; ni++) {
            int ncol = n0 + wn * 32 + ni * 8 + (lane & 3) * 2;
            *(float2*)&C[(size_t)mrow * N + ncol] =
                make_float2(acc[mi][ni][0], acc[mi][ni][1]);
            *(float2*)&C[(size_t)(mrow + 8) * N + ncol] =
                make_float2(acc[mi][ni][2], acc[mi][ni][3]);
        }
    }
}

// ============================================================================
// RoPE -> fp16 2-term attention operands (unchanged from R7)
// ============================================================================
__global__ __launch_bounds__(256) void rope_pack_kernel(
    const float* __restrict__ qkv,
    const float* __restrict__ sin_q, const float* __restrict__ cos_q,
    const float* __restrict__ sin_k, const float* __restrict__ cos_k,
    __half* __restrict__ Qp, __half* __restrict__ Kp, __half* __restrict__ Vph)
{
    int idx = blockIdx.x * blockDim.x + threadIdx.x;
    if (idx >= B_*S_*D_) return;
    int d = idx % HD_;
    int h = (idx / HD_) % H_;
    int s = (idx / D_) % S_;
    int b = idx / (S_ * D_);

    const float* row = qkv + ((size_t)b*S_ + s) * (3*D_);
    int hd = h*HD_ + d;
    int dp = (d < HD_/2) ? d + HD_/2 : d - HD_/2;
    float sgn = (d < HD_/2) ? -1.f : 1.f;

    float qv = row[hd];
    float kv = row[D_ + hd];
    float vv = row[2*D_ + hd];
    float qp = row[h*HD_ + dp];
    float kp = row[D_ + h*HD_ + dp];

    float sq = sin_q[s*HD_ + d], cq = cos_q[s*HD_ + d];
    float sk = sin_k[s*HD_ + d], ck = cos_k[s*HD_ + d];

    float qr = (qv * cq + sgn * qp * sq) * SCALE_;
    float kr = kv * ck + sgn * kp * sk;

    size_t bhs = ((size_t)(b*H_ + h) * S_ + s);

    __half qh = __float2half_rn(qr);
    __half ql = __float2half_rn(qr - __half2float(qh));
    __half kh = __float2half_rn(kr);

    __half* qrow = Qp + bhs * AKP_;
    qrow[d] = qh; qrow[64 + d] = ql;
    __half* krow = Kp + bhs * AKP_;
    krow[d] = kh; krow[64 + d] = kh;
    Vph[bhs * HD_ + d] = __float2half_rn(vv);
}

// ============================================================================
// Tensor-core causal flash attention (R7 mainloop, known-good).
// Epilogue writes plain fp16 A rows for the out-projection (K=1024).
// ============================================================================
#define AQ 128
#define AK 32
#define QSTR 136   // halves per Q/K smem row (128 + 8 pad)
#define VSTR 72    // halves per V smem row (64 + 8 pad)

#define QS_OFF   0
#define KS_OFF   17408           // 128*136
#define KS_STAGE 4352            // 32*136
#define VH_OFF   26112           // KS_OFF + 2*KS_STAGE
#define VS_STAGE 2304            // 32*72
#define ATTN_SMEM_BYTES ((VH_OFF + 2*VS_STAGE) * 2)   // 61440

__global__ __launch_bounds__(128) void attn_mma_kernel(
    const __half* __restrict__ Qp, const __half* __restrict__ Kp,
    const __half* __restrict__ Vph,
    __half* __restrict__ Aout)   // [B*S, D] fp16
{
    extern __shared__ __align__(16) __half sm[];
    const uint32_t smb = smem_u32(sm);

    const int tid  = threadIdx.x;
    const int wid  = tid >> 5, lane = tid & 31;
    const int bh   = blockIdx.y;
    const int q0   = blockIdx.x * AQ;
    const int qrow0 = q0 + 32 * wid;

    const size_t bhS = (size_t)bh * S_;

    auto load_q = [&]() {
        #pragma unroll
        for (int i = 0; i < 16; i++) {
            int idx = tid + i * 128;
            int row = idx >> 4, c = idx & 15;
            CP_ASYNC16(smb + (uint32_t)(QS_OFF + row * QSTR + c * 8) * 2,
                       Qp + (bhS + q0 + row) * AKP_ + c * 8);
        }
    };
    auto load_kv = [&](int stage, int kt) {
        int s0 = kt * AK;
        #pragma unroll
        for (int i = 0; i < 4; i++) {
            int idx = tid + i * 128;
            int row = idx >> 4, c = idx & 15;
            CP_ASYNC16(smb + (uint32_t)(KS_OFF + stage * KS_STAGE + row * QSTR + c * 8) * 2,
                       Kp + (bhS + s0 + row) * AKP_ + c * 8);
        }
        #pragma unroll
        for (int i = 0; i < 2; i++) {
            int idx = tid + i * 128;
            int row = idx >> 3, c = idx & 7;
            CP_ASYNC16(smb + (uint32_t)(VH_OFF + stage * VS_STAGE + row * VSTR + c * 8) * 2,
                       Vph + (bhS + s0 + row) * HD_ + c * 8);
        }
    };

    float O[2][8][4];
    #pragma unroll
    for (int mi = 0; mi < 2; mi++)
        #pragma unroll
        for (int nd = 0; nd < 8; nd++)
            #pragma unroll
            for (int r = 0; r < 4; r++) O[mi][nd][r] = 0.f;
    float mst[2][2] = {{-CUDART_INF_F, -CUDART_INF_F}, {-CUDART_INF_F, -CUDART_INF_F}};
    float lst[2][2] = {{0.f, 0.f}, {0.f, 0.f}};

    const int ntiles = q0 / AK + 4;

    load_q();
    CP_COMMIT();
    load_kv(0, 0);
    CP_COMMIT();

    for (int kt = 0; kt < ntiles; kt++) {
        const int stage = kt & 1;
        if (kt + 1 < ntiles) {
            load_kv((kt + 1) & 1, kt + 1);
            CP_COMMIT();
            CP_WAIT1();
        } else {
            CP_WAIT0();
        }
        __syncthreads();

        const int k0g = kt * AK;
        const bool active = (k0g <= qrow0 + 31);

        if (active) {
            float c[2][4][4];
            #pragma unroll
            for (int mi = 0; mi < 2; mi++)
                #pragma unroll
                for (int ni = 0; ni < 4; ni++)
                    #pragma unroll
                    for (int r = 0; r < 4; r++) c[mi][ni][r] = 0.f;

            #pragma unroll
            for (int kc = 0; kc < 8; kc++) {
                uint32_t kb[4][2];
                #pragma unroll
                for (int t = 0; t < 2; t++) {
                    int krow = 16*t + (lane & 7) + 8*(lane >> 4);
                    int kcol = kc*16 + 8*((lane >> 3) & 1);
                    uint32_t r0, r1, r2, r3;
                    LDMATRIX_X4(r0, r1, r2, r3,
                        smb + (uint32_t)(KS_OFF + stage*KS_STAGE + krow*QSTR + kcol) * 2);
                    kb[2*t][0] = r0; kb[2*t][1] = r1;
                    kb[2*t+1][0] = r2; kb[2*t+1][1] = r3;
                }
                #pragma unroll
                for (int mi = 0; mi < 2; mi++) {
                    int qrow = 32*wid + 16*mi + (lane & 15);
                    int qcol = kc*16 + 8*(lane >> 4);
                    uint32_t a0, a1, a2, a3;
                    LDMATRIX_X4(a0, a1, a2, a3,
                        smb + (uint32_t)(QS_OFF + qrow*QSTR + qcol) * 2);
                    #pragma unroll
                    for (int ni = 0; ni < 4; ni++)
                        MMA_F16(c[mi][ni][0], c[mi][ni][1], c[mi][ni][2], c[mi][ni][3],
                                a0, a1, a2, a3, kb[ni][0], kb[ni][1]);
                }
            }

            if (k0g + AK - 1 > qrow0) {
                #pragma unroll
                for (int mi = 0; mi < 2; mi++)
                    #pragma unroll
                    for (int ni = 0; ni < 4; ni++)
                        #pragma unroll
                        for (int r = 0; r < 4; r++) {
                            int kk = k0g + ni*8 + 2*(lane & 3) + (r & 1);
                            int qq = qrow0 + 16*mi + (lane >> 2) + ((r >= 2) ? 8 : 0);
                            if (kk > qq) c[mi][ni][r] = -CUDART_INF_F;
                        }
            }

            #pragma unroll
            for (int mi = 0; mi < 2; mi++)
                #pragma unroll
                for (int h = 0; h < 2; h++) {
                    float mt = -CUDART_INF_F;
                    #pragma unroll
                    for (int ni = 0; ni < 4; ni++)
                        mt = fmaxf(mt, fmaxf(c[mi][ni][2*h], c[mi][ni][2*h+1]));
                    mt = fmaxf(mt, __shfl_xor_sync(0xffffffffu, mt, 1));
                    mt = fmaxf(mt, __shfl_xor_sync(0xffffffffu, mt, 2));
                    float mnew = fmaxf(mst[mi][h], mt);
                    float corr = __expf(mst[mi][h] - mnew);
                    mst[mi][h] = mnew;
                    float ls = 0.f;
                    #pragma unroll
                    for (int ni = 0; ni < 4; ni++) {
                        float p0 = __expf(c[mi][ni][2*h]   - mnew);
                        float p1 = __expf(c[mi][ni][2*h+1] - mnew);
                        c[mi][ni][2*h] = p0; c[mi][ni][2*h+1] = p1;
                        ls += p0 + p1;
                    }
                    lst[mi][h] = lst[mi][h] * corr + ls;
                    #pragma unroll
                    for (int nd = 0; nd < 8; nd++) {
                        O[mi][nd][2*h]   *= corr;
                        O[mi][nd][2*h+1] *= corr;
                    }
                }

            // ---- PV: (Ph + Pl) x fp16(V), 2 MMAs ----
            #pragma unroll
            for (int kc2 = 0; kc2 < 2; kc2++) {
                uint32_t ph[2][4], pl[2][4];
                #pragma unroll
                for (int mi = 0; mi < 2; mi++) {
                    pack_pair_h(c[mi][2*kc2][0],   c[mi][2*kc2][1],   ph[mi][0], pl[mi][0]);
                    pack_pair_h(c[mi][2*kc2][2],   c[mi][2*kc2][3],   ph[mi][1], pl[mi][1]);
                    pack_pair_h(c[mi][2*kc2+1][0], c[mi][2*kc2+1][1], ph[mi][2], pl[mi][2]);
                    pack_pair_h(c[mi][2*kc2+1][2], c[mi][2*kc2+1][3], ph[mi][3], pl[mi][3]);
                }
                uint32_t vh[8][2];
                #pragma unroll
                for (int t = 0; t < 4; t++) {
                    int vrow = kc2*16 + (lane & 15);
                    int vcol = 16*t + 8*(lane >> 4);
                    uint32_t r0, r1, r2, r3;
                    LDMATRIX_X4_T(r0, r1, r2, r3,
                        smb + (uint32_t)(VH_OFF + stage*VS_STAGE + vrow*VSTR + vcol) * 2);
                    vh[2*t][0] = r0; vh[2*t][1] = r1;
                    vh[2*t+1][0] = r2; vh[2*t+1][1] = r3;
                }
                #pragma unroll
                for (int mi = 0; mi < 2; mi++)
                    #pragma unroll
                    for (int nd = 0; nd < 8; nd++) {
                        MMA_F16(O[mi][nd][0], O[mi][nd][1], O[mi][nd][2], O[mi][nd][3],
                                ph[mi][0], ph[mi][1], ph[mi][2], ph[mi][3],
                                vh[nd][0], vh[nd][1]);
                        MMA_F16(O[mi][nd][0], O[mi][nd][1], O[mi][nd][2], O[mi][nd][3],
                                pl[mi][0], pl[mi][1], pl[mi][2], pl[mi][3],
                                vh[nd][0], vh[nd][1]);
                    }
            }
        }
        __syncthreads();
    }

    // ---- normalize + write plain fp16 A rows for out-proj ----
    const int b = bh >> 4, hh = bh & 15;
    #pragma unroll
    for (int mi = 0; mi < 2; mi++)
        #pragma unroll
        for (int h = 0; h < 2; h++) {
            float lt = lst[mi][h];
            lt += __shfl_xor_sync(0xffffffffu, lt, 1);
            lt += __shfl_xor_sync(0xffffffffu, lt, 2);
            float inv = 1.f / lt;
            int row = qrow0 + 16*mi + (lane >> 2) + ((h) ? 8 : 0);
            size_t rbase = ((size_t)b*S_ + row) * D_;
            #pragma unroll
            for (int nd = 0; nd < 8; nd++) {
                int col = hh * HD_ + nd*8 + 2*(lane & 3);
                *(uint32_t*)&Aout[rbase + col] =
                    pack2h(O[mi][nd][2*h] * inv, O[mi][nd][2*h+1] * inv);
            }
        }
}

// ============================================================================
// Launch
// ============================================================================
extern "C" void kernel_launch(void* const* d_in, const int* in_sizes, int n_in,
                              void* d_out, int out_size)
{
    const float* query = (const float*)d_in[0];
    const float* sin_q = (const float*)d_in[1];
    const float* cos_q = (const float*)d_in[2];
    const float* sin_k = (const float*)d_in[3];
    const float* cos_k = (const float*)d_in[4];
    const float* w_in  = (const float*)d_in[5];
    const float* w_out = (const float*)d_in[6];
    float* out = (float*)d_out;

    float *qkv;
    __half *A, *W1t, *W2t, *Qp, *Kp, *Vph;
    cudaGetSymbolAddress((void**)&qkv, g_qkv);
    cudaGetSymbolAddress((void**)&A,   g_A);
    cudaGetSymbolAddress((void**)&W1t, g_W1t);
    cudaGetSymbolAddress((void**)&W2t, g_W2t);
    cudaGetSymbolAddress((void**)&Qp,  g_Qp);
    cudaGetSymbolAddress((void**)&Kp,  g_Kp);
    cudaGetSymbolAddress((void**)&Vph, g_Vph);

    static bool attr_set = false;
    if (!attr_set) {
        cudaFuncSetAttribute(attn_mma_kernel,
                             cudaFuncAttributeMaxDynamicSharedMemorySize, ATTN_SMEM_BYTES);
        attr_set = true;
    }

    const int M = B_ * S_;   // 4096

    // Prep: fp16 casts
    cast_a_kernel<<<(M*D_ + 255)/256, 256>>>(query, A, M*D_);
    transpose_cast_w_kernel<<<dim3(3*D_/32, D_/32), dim3(32,8)>>>(w_in,  W1t, 3*D_);
    transpose_cast_w_kernel<<<dim3(D_/32,   D_/32), dim3(32,8)>>>(w_out, W2t, D_);

    // 1) QKV projection (plain fp16, K=1024)
    gemm_mma_kernel<<<dim3(3*D_/GBN, M/GBM), 256>>>(A, W1t, qkv, M, 3*D_);

    // 2) RoPE + pack fp16 2-term attention operands
    rope_pack_kernel<<<(B_*S_*D_ + 255)/256, 256>>>(
        qkv, sin_q, cos_q, sin_k, cos_k, Qp, Kp, Vph);

    // 3) Tensor-core causal flash attention (writes fp16 A rows directly)
    attn_mma_kernel<<<dim3(S_/AQ, B_*H_), 128, ATTN_SMEM_BYTES>>>(Qp, Kp, Vph, A);

    // 4) Output projection (plain fp16, K=1024)
    gemm_mma_kernel<<<dim3(D_/GBN, M/GBM), 256>>>(A, W2t, out, M, D_);
}

// round 9
// speedup vs baseline: 2.3399x; 1.1275x over previous
#include <cuda_runtime.h>
#include <cuda_fp16.h>
#include <math_constants.h>
#include <cstdint>

// Problem constants
#define B_   2
#define S_   2048
#define D_   1024
#define H_   16
#define HD_  64
#define SCALE_ 0.125f   // 1/sqrt(64)
#define KPG_ D_         // plain fp16 GEMM K = 1024

// ============================================================================
// Static device scratch
// ============================================================================
__device__ float g_qkv [(size_t)(B_*S_) * (3*D_)];
__device__ __half g_A   [(size_t)(B_*S_) * D_];         // [4096, 1024] fp16
__device__ __half g_W1t [(size_t)(3*D_) * D_];          // [3072, 1024] fp16 (N-major)
__device__ __half g_W2t [(size_t)D_ * D_];              // [1024, 1024] fp16 (N-major)
__device__ __half g_Qp [(size_t)B_*H_*S_*HD_];          // fp16(scale*rope(q))
__device__ __half g_Kp [(size_t)B_*H_*S_*HD_];          // fp16(rope(k))
__device__ __half g_Vph[(size_t)B_*H_*S_*HD_];          // fp16(v)

// ============================================================================
// PTX helpers (sm_80-era only — safe for compute_103 baseline PTX)
// ============================================================================
__device__ __forceinline__ uint32_t smem_u32(const void* p) {
    uint32_t a;
    asm("{ .reg .u64 t; cvta.to.shared.u64 t, %1; cvt.u32.u64 %0, t; }" : "=r"(a) : "l"(p));
    return a;
}
#define CP_ASYNC16(saddr, gptr) \
    asm volatile("cp.async.cg.shared.global [%0], [%1], 16;" :: "r"(saddr), "l"(gptr))
#define CP_COMMIT() asm volatile("cp.async.commit_group;" ::: "memory")
#define CP_WAIT1()  asm volatile("cp.async.wait_group 1;" ::: "memory")
#define CP_WAIT0()  asm volatile("cp.async.wait_group 0;" ::: "memory")
#define LDMATRIX_X4(r0, r1, r2, r3, addr) \
    asm volatile("ldmatrix.sync.aligned.m8n8.x4.shared.b16 {%0,%1,%2,%3}, [%4];" \
        : "=r"(r0), "=r"(r1), "=r"(r2), "=r"(r3) : "r"(addr))
#define LDMATRIX_X4_T(r0, r1, r2, r3, addr) \
    asm volatile("ldmatrix.sync.aligned.m8n8.x4.trans.shared.b16 {%0,%1,%2,%3}, [%4];" \
        : "=r"(r0), "=r"(r1), "=r"(r2), "=r"(r3) : "r"(addr))
#define MMA_F16(c0, c1, c2, c3, a0, a1, a2, a3, b0, b1) \
    asm volatile("mma.sync.aligned.m16n8k16.row.col.f32.f16.f16.f32 " \
        "{%0,%1,%2,%3}, {%4,%5,%6,%7}, {%8,%9}, {%0,%1,%2,%3};" \
        : "+f"(c0), "+f"(c1), "+f"(c2), "+f"(c3) \
        : "r"(a0), "r"(a1), "r"(a2), "r"(a3), "r"(b0), "r"(b1))

__device__ __forceinline__ uint32_t pack2h(float p0, float p1) {
    __half h0 = __float2half_rn(p0), h1 = __float2half_rn(p1);
    return ((uint32_t)__half_as_ushort(h1) << 16) | (uint32_t)__half_as_ushort(h0);
}

// ============================================================================
// Prep: plain fp16 casts
// ============================================================================
__global__ __launch_bounds__(256) void cast_a_kernel(
    const float* __restrict__ x, __half* __restrict__ out, int total)
{
    int i = blockIdx.x * blockDim.x + threadIdx.x;
    if (i >= total) return;
    out[i] = __float2half_rn(x[i]);
}

// w[K=1024][N] -> out[N][1024] fp16
__global__ __launch_bounds__(256) void transpose_cast_w_kernel(
    const float* __restrict__ w, __half* __restrict__ out, int N)
{
    __shared__ float tile[32][33];
    int k0 = blockIdx.y * 32, n0 = blockIdx.x * 32;
    int tx = threadIdx.x, ty = threadIdx.y;
    #pragma unroll
    for (int i = 0; i < 32; i += 8)
        tile[ty + i][tx] = w[(size_t)(k0 + ty + i) * N + n0 + tx];
    __syncthreads();
    #pragma unroll
    for (int i = 0; i < 32; i += 8)
        out[(size_t)(n0 + ty + i) * KPG_ + k0 + tx] = __float2half_rn(tile[tx][ty + i]);
}

// ============================================================================
// fp16 mma.sync GEMM (unchanged from R8 — known-good)
// ============================================================================
#define GBM 128
#define GBN 128
#define GBK 32
#define SSTRIDE 40

__global__ __launch_bounds__(256) void gemm_mma_kernel(
    const __half* __restrict__ A,
    const __half* __restrict__ W,
    float* __restrict__ C, int M, int N)
{
    __shared__ __half As[2][GBM * SSTRIDE];
    __shared__ __half Bs[2][GBN * SSTRIDE];

    const int tid  = threadIdx.x;
    const int wid  = tid >> 5, lane = tid & 31;
    const int m0   = blockIdx.y * GBM;
    const int n0   = blockIdx.x * GBN;
    const int wm   = wid >> 2;
    const int wn   = wid & 3;

    float acc[4][4][4];
    #pragma unroll
    for (int mi = 0; mi < 4; mi++)
        #pragma unroll
        for (int ni = 0; ni < 4; ni++)
            #pragma unroll
            for (int r = 0; r < 4; r++) acc[mi][ni][r] = 0.f;

    const uint32_t as0 = smem_u32(&As[0][0]), as1 = smem_u32(&As[1][0]);
    const uint32_t bs0 = smem_u32(&Bs[0][0]), bs1 = smem_u32(&Bs[1][0]);

    const int lr0 = tid >> 2,          lc0 = (tid & 3);
    const int lr1 = (tid + 256) >> 2,  lc1 = (tid & 3);

    auto load_stage = [&](int stage, int kb) {
        const int kt = kb * GBK;
        const uint32_t as = stage ? as1 : as0;
        const uint32_t bs = stage ? bs1 : bs0;
        CP_ASYNC16(as + (uint32_t)(lr0 * SSTRIDE + lc0 * 8) * 2,
                   A + (size_t)(m0 + lr0) * KPG_ + kt + lc0 * 8);
        CP_ASYNC16(as + (uint32_t)(lr1 * SSTRIDE + lc1 * 8) * 2,
                   A + (size_t)(m0 + lr1) * KPG_ + kt + lc1 * 8);
        CP_ASYNC16(bs + (uint32_t)(lr0 * SSTRIDE + lc0 * 8) * 2,
                   W + (size_t)(n0 + lr0) * KPG_ + kt + lc0 * 8);
        CP_ASYNC16(bs + (uint32_t)(lr1 * SSTRIDE + lc1 * 8) * 2,
                   W + (size_t)(n0 + lr1) * KPG_ + kt + lc1 * 8);
    };

    const int NKB = KPG_ / GBK;   // 32
    load_stage(0, 0);
    CP_COMMIT();

    for (int kb = 0; kb < NKB; kb++) {
        if (kb + 1 < NKB) {
            load_stage((kb + 1) & 1, kb + 1);
            CP_COMMIT();
            CP_WAIT1();
        } else {
            CP_WAIT0();
        }
        __syncthreads();

        const uint32_t as = (kb & 1) ? as1 : as0;
        const uint32_t bs = (kb & 1) ? bs1 : bs0;

        #pragma unroll
        for (int ks = 0; ks < 2; ks++) {
            uint32_t a[4][4];
            #pragma unroll
            for (int mi = 0; mi < 4; mi++) {
                int row = wm * 64 + mi * 16 + (lane & 15);
                int col = ks * 16 + (lane >> 4) * 8;
                LDMATRIX_X4(a[mi][0], a[mi][1], a[mi][2], a[mi][3],
                            as + (uint32_t)(row * SSTRIDE + col) * 2);
            }
            uint32_t b[4][2];
            #pragma unroll
            for (int nb = 0; nb < 2; nb++) {
                int nrow = wn * 32 + nb * 16 + ((lane & 16) ? 8 : 0) + (lane & 7);
                int kcol = ks * 16 + ((lane & 8) ? 8 : 0);
                uint32_t r0, r1, r2, r3;
                LDMATRIX_X4(r0, r1, r2, r3,
                            bs + (uint32_t)(nrow * SSTRIDE + kcol) * 2);
                b[nb*2][0] = r0; b[nb*2][1] = r1;
                b[nb*2+1][0] = r2; b[nb*2+1][1] = r3;
            }
            #pragma unroll
            for (int mi = 0; mi < 4; mi++)
                #pragma unroll
                for (int ni = 0; ni < 4; ni++)
                    MMA_F16(acc[mi][ni][0], acc[mi][ni][1], acc[mi][ni][2], acc[mi][ni][3],
                            a[mi][0], a[mi][1], a[mi][2], a[mi][3],
                            b[ni][0], b[ni][1]);
        }
        __syncthreads();
    }

    #pragma unroll
    for (int mi = 0; mi < 4; mi++) {
        int mrow = m0 + wm * 64 + mi * 16 + (lane >> 2);
        #pragma unroll
        for (int ni = 0; ni < 4; ni++) {
            int ncol = n0 + wn * 32 + ni * 8 + (lane & 3) * 2;
            *(float2*)&C[(size_t)mrow * N + ncol] =
                make_float2(acc[mi][ni][0], acc[mi][ni][1]);
            *(float2*)&C[(size_t)(mrow + 8) * N + ncol] =
                make_float2(acc[mi][ni][2], acc[mi][ni][3]);
        }
    }
}

// ============================================================================
// RoPE -> plain fp16 attention operands (Q scale-folded)
// ============================================================================
__global__ __launch_bounds__(256) void rope_pack_kernel(
    const float* __restrict__ qkv,
    const float* __restrict__ sin_q, const float* __restrict__ cos_q,
    const float* __restrict__ sin_k, const float* __restrict__ cos_k,
    __half* __restrict__ Qp, __half* __restrict__ Kp, __half* __restrict__ Vph)
{
    int idx = blockIdx.x * blockDim.x + threadIdx.x;
    if (idx >= B_*S_*D_) return;
    int d = idx % HD_;
    int h = (idx / HD_) % H_;
    int s = (idx / D_) % S_;
    int b = idx / (S_ * D_);

    const float* row = qkv + ((size_t)b*S_ + s) * (3*D_);
    int hd = h*HD_ + d;
    int dp = (d < HD_/2) ? d + HD_/2 : d - HD_/2;
    float sgn = (d < HD_/2) ? -1.f : 1.f;

    float qv = row[hd];
    float kv = row[D_ + hd];
    float vv = row[2*D_ + hd];
    float qp = row[h*HD_ + dp];
    float kp = row[D_ + h*HD_ + dp];

    float sq = sin_q[s*HD_ + d], cq = cos_q[s*HD_ + d];
    float sk = sin_k[s*HD_ + d], ck = cos_k[s*HD_ + d];

    float qr = (qv * cq + sgn * qp * sq) * SCALE_;
    float kr = kv * ck + sgn * kp * sk;

    size_t o = ((size_t)(b*H_ + h) * S_ + s) * HD_ + d;
    Qp[o]  = __float2half_rn(qr);
    Kp[o]  = __float2half_rn(kr);
    Vph[o] = __float2half_rn(vv);
}

// ============================================================================
// Tensor-core causal flash attention, plain fp16 (Q,K,V,P all fp16, fp32 acc).
// CTA: 128 queries x one (b,h), 4 warps x 32 rows, 32-key tiles, 2-stage
// cp.async. Static 36.9KB smem. Epilogue writes fp16 A rows for out-proj.
// ============================================================================
#define AQ 128
#define AK 32
#define QSTR 72    // halves per row (64 + 8 pad)

#define QS_OFF   0
#define KS_OFF   9216            // 128*72
#define KS_STAGE 2304            // 32*72
#define VH_OFF   13824           // KS_OFF + 2*KS_STAGE
#define VS_STAGE 2304
#define ATTN_SMEM_ELEMS (VH_OFF + 2*VS_STAGE)   // 18432 halves = 36864 B

__global__ __launch_bounds__(128) void attn_mma_kernel(
    const __half* __restrict__ Qp, const __half* __restrict__ Kp,
    const __half* __restrict__ Vph,
    __half* __restrict__ Aout)   // [B*S, D] fp16
{
    __shared__ __align__(16) __half sm[ATTN_SMEM_ELEMS];
    const uint32_t smb = smem_u32(sm);

    const int tid  = threadIdx.x;
    const int wid  = tid >> 5, lane = tid & 31;
    const int bh   = blockIdx.y;
    const int q0   = blockIdx.x * AQ;
    const int qrow0 = q0 + 32 * wid;

    const size_t bhS = (size_t)bh * S_;

    auto load_q = [&]() {
        #pragma unroll
        for (int i = 0; i < 8; i++) {            // 128 rows x 8 float4
            int idx = tid + i * 128;
            int row = idx >> 3, c = idx & 7;
            CP_ASYNC16(smb + (uint32_t)(QS_OFF + row * QSTR + c * 8) * 2,
                       Qp + (bhS + q0 + row) * HD_ + c * 8);
        }
    };
    auto load_kv = [&](int stage, int kt) {
        int s0 = kt * AK;
        #pragma unroll
        for (int i = 0; i < 2; i++) {            // 32 rows x 8 float4
            int idx = tid + i * 128;
            int row = idx >> 3, c = idx & 7;
            CP_ASYNC16(smb + (uint32_t)(KS_OFF + stage * KS_STAGE + row * QSTR + c * 8) * 2,
                       Kp + (bhS + s0 + row) * HD_ + c * 8);
            CP_ASYNC16(smb + (uint32_t)(VH_OFF + stage * VS_STAGE + row * QSTR + c * 8) * 2,
                       Vph + (bhS + s0 + row) * HD_ + c * 8);
        }
    };

    float O[2][8][4];
    #pragma unroll
    for (int mi = 0; mi < 2; mi++)
        #pragma unroll
        for (int nd = 0; nd < 8; nd++)
            #pragma unroll
            for (int r = 0; r < 4; r++) O[mi][nd][r] = 0.f;
    float mst[2][2] = {{-CUDART_INF_F, -CUDART_INF_F}, {-CUDART_INF_F, -CUDART_INF_F}};
    float lst[2][2] = {{0.f, 0.f}, {0.f, 0.f}};

    const int ntiles = q0 / AK + 4;

    load_q();
    CP_COMMIT();
    load_kv(0, 0);
    CP_COMMIT();

    for (int kt = 0; kt < ntiles; kt++) {
        const int stage = kt & 1;
        if (kt + 1 < ntiles) {
            load_kv((kt + 1) & 1, kt + 1);
            CP_COMMIT();
            CP_WAIT1();
        } else {
            CP_WAIT0();
        }
        __syncthreads();

        const int k0g = kt * AK;
        const bool active = (k0g <= qrow0 + 31);

        if (active) {
            float c[2][4][4];
            #pragma unroll
            for (int mi = 0; mi < 2; mi++)
                #pragma unroll
                for (int ni = 0; ni < 4; ni++)
                    #pragma unroll
                    for (int r = 0; r < 4; r++) c[mi][ni][r] = 0.f;

            #pragma unroll
            for (int kc = 0; kc < 4; kc++) {     // HD=64 -> 4 k16 chunks
                uint32_t kb[4][2];
                #pragma unroll
                for (int t = 0; t < 2; t++) {
                    int krow = 16*t + (lane & 7) + 8*(lane >> 4);
                    int kcol = kc*16 + 8*((lane >> 3) & 1);
                    uint32_t r0, r1, r2, r3;
                    LDMATRIX_X4(r0, r1, r2, r3,
                        smb + (uint32_t)(KS_OFF + stage*KS_STAGE + krow*QSTR + kcol) * 2);
                    kb[2*t][0] = r0; kb[2*t][1] = r1;
                    kb[2*t+1][0] = r2; kb[2*t+1][1] = r3;
                }
                #pragma unroll
                for (int mi = 0; mi < 2; mi++) {
                    int qrow = 32*wid + 16*mi + (lane & 15);
                    int qcol = kc*16 + 8*(lane >> 4);
                    uint32_t a0, a1, a2, a3;
                    LDMATRIX_X4(a0, a1, a2, a3,
                        smb + (uint32_t)(QS_OFF + qrow*QSTR + qcol) * 2);
                    #pragma unroll
                    for (int ni = 0; ni < 4; ni++)
                        MMA_F16(c[mi][ni][0], c[mi][ni][1], c[mi][ni][2], c[mi][ni][3],
                                a0, a1, a2, a3, kb[ni][0], kb[ni][1]);
                }
            }

            if (k0g + AK - 1 > qrow0) {
                #pragma unroll
                for (int mi = 0; mi < 2; mi++)
                    #pragma unroll
                    for (int ni = 0; ni < 4; ni++)
                        #pragma unroll
                        for (int r = 0; r < 4; r++) {
                            int kk = k0g + ni*8 + 2*(lane & 3) + (r & 1);
                            int qq = qrow0 + 16*mi + (lane >> 2) + ((r >= 2) ? 8 : 0);
                            if (kk > qq) c[mi][ni][r] = -CUDART_INF_F;
                        }
            }

            #pragma unroll
            for (int mi = 0; mi < 2; mi++)
                #pragma unroll
                for (int h = 0; h < 2; h++) {
                    float mt = -CUDART_INF_F;
                    #pragma unroll
                    for (int ni = 0; ni < 4; ni++)
                        mt = fmaxf(mt, fmaxf(c[mi][ni][2*h], c[mi][ni][2*h+1]));
                    mt = fmaxf(mt, __shfl_xor_sync(0xffffffffu, mt, 1));
                    mt = fmaxf(mt, __shfl_xor_sync(0xffffffffu, mt, 2));
                    float mnew = fmaxf(mst[mi][h], mt);
                    float corr = __expf(mst[mi][h] - mnew);
                    mst[mi][h] = mnew;
                    float ls = 0.f;
                    #pragma unroll
                    for (int ni = 0; ni < 4; ni++) {
                        float p0 = __expf(c[mi][ni][2*h]   - mnew);
                        float p1 = __expf(c[mi][ni][2*h+1] - mnew);
                        c[mi][ni][2*h] = p0; c[mi][ni][2*h+1] = p1;
                        ls += p0 + p1;
                    }
                    lst[mi][h] = lst[mi][h] * corr + ls;
                    #pragma unroll
                    for (int nd = 0; nd < 8; nd++) {
                        O[mi][nd][2*h]   *= corr;
                        O[mi][nd][2*h+1] *= corr;
                    }
                }

            // ---- PV: fp16(P) x fp16(V), 1 MMA per (mi,nd,kc2) ----
            #pragma unroll
            for (int kc2 = 0; kc2 < 2; kc2++) {
                uint32_t ph[2][4];
                #pragma unroll
                for (int mi = 0; mi < 2; mi++) {
                    ph[mi][0] = pack2h(c[mi][2*kc2][0],   c[mi][2*kc2][1]);
                    ph[mi][1] = pack2h(c[mi][2*kc2][2],   c[mi][2*kc2][3]);
                    ph[mi][2] = pack2h(c[mi][2*kc2+1][0], c[mi][2*kc2+1][1]);
                    ph[mi][3] = pack2h(c[mi][2*kc2+1][2], c[mi][2*kc2+1][3]);
                }
                uint32_t vh[8][2];
                #pragma unroll
                for (int t = 0; t < 4; t++) {
                    int vrow = kc2*16 + (lane & 15);
                    int vcol = 16*t + 8*(lane >> 4);
                    uint32_t r0, r1, r2, r3;
                    LDMATRIX_X4_T(r0, r1, r2, r3,
                        smb + (uint32_t)(VH_OFF + stage*VS_STAGE + vrow*QSTR + vcol) * 2);
                    vh[2*t][0] = r0; vh[2*t][1] = r1;
                    vh[2*t+1][0] = r2; vh[2*t+1][1] = r3;
                }
                #pragma unroll
                for (int mi = 0; mi < 2; mi++)
                    #pragma unroll
                    for (int nd = 0; nd < 8; nd++)
                        MMA_F16(O[mi][nd][0], O[mi][nd][1], O[mi][nd][2], O[mi][nd][3],
                                ph[mi][0], ph[mi][1], ph[mi][2], ph[mi][3],
                                vh[nd][0], vh[nd][1]);
            }
        }
        __syncthreads();
    }

    // ---- normalize + write plain fp16 A rows for out-proj ----
    const int b = bh >> 4, hh = bh & 15;
    #pragma unroll
    for (int mi = 0; mi < 2; mi++)
        #pragma unroll
        for (int h = 0; h < 2; h++) {
            float lt = lst[mi][h];
            lt += __shfl_xor_sync(0xffffffffu, lt, 1);
            lt += __shfl_xor_sync(0xffffffffu, lt, 2);
            float inv = 1.f / lt;
            int row = qrow0 + 16*mi + (lane >> 2) + ((h) ? 8 : 0);
            size_t rbase = ((size_t)b*S_ + row) * D_;
            #pragma unroll
            for (int nd = 0; nd < 8; nd++) {
                int col = hh * HD_ + nd*8 + 2*(lane & 3);
                *(uint32_t*)&Aout[rbase + col] =
                    pack2h(O[mi][nd][2*h] * inv, O[mi][nd][2*h+1] * inv);
            }
        }
}

// ============================================================================
// Launch
// ============================================================================
extern "C" void kernel_launch(void* const* d_in, const int* in_sizes, int n_in,
                              void* d_out, int out_size)
{
    const float* query = (const float*)d_in[0];
    const float* sin_q = (const float*)d_in[1];
    const float* cos_q = (const float*)d_in[2];
    const float* sin_k = (const float*)d_in[3];
    const float* cos_k = (const float*)d_in[4];
    const float* w_in  = (const float*)d_in[5];
    const float* w_out = (const float*)d_in[6];
    float* out = (float*)d_out;

    float *qkv;
    __half *A, *W1t, *W2t, *Qp, *Kp, *Vph;
    cudaGetSymbolAddress((void**)&qkv, g_qkv);
    cudaGetSymbolAddress((void**)&A,   g_A);
    cudaGetSymbolAddress((void**)&W1t, g_W1t);
    cudaGetSymbolAddress((void**)&W2t, g_W2t);
    cudaGetSymbolAddress((void**)&Qp,  g_Qp);
    cudaGetSymbolAddress((void**)&Kp,  g_Kp);
    cudaGetSymbolAddress((void**)&Vph, g_Vph);

    const int M = B_ * S_;   // 4096

    // Prep: fp16 casts
    cast_a_kernel<<<(M*D_ + 255)/256, 256>>>(query, A, M*D_);
    transpose_cast_w_kernel<<<dim3(3*D_/32, D_/32), dim3(32,8)>>>(w_in,  W1t, 3*D_);
    transpose_cast_w_kernel<<<dim3(D_/32,   D_/32), dim3(32,8)>>>(w_out, W2t, D_);

    // 1) QKV projection (plain fp16, K=1024)
    gemm_mma_kernel<<<dim3(3*D_/GBN, M/GBM), 256>>>(A, W1t, qkv, M, 3*D_);

    // 2) RoPE + pack fp16 attention operands
    rope_pack_kernel<<<(B_*S_*D_ + 255)/256, 256>>>(
        qkv, sin_q, cos_q, sin_k, cos_k, Qp, Kp, Vph);

    // 3) Tensor-core causal flash attention (plain fp16)
    attn_mma_kernel<<<dim3(S_/AQ, B_*H_), 128>>>(Qp, Kp, Vph, A);

    // 4) Output projection (plain fp16, K=1024)
    gemm_mma_kernel<<<dim3(D_/GBN, M/GBM), 256>>>(A, W2t, out, M, D_);
}